// round 10
// baseline (speedup 1.0000x reference)
#include <cuda_runtime.h>
#include <math.h>

// Problem constants
#define NIMG 512          // B*C
#define NALL 1024         // pred + gt images

// Output offsets (tuple order, flattened)
#define OFF_E    0
#define OFF_U    524288
#define OFF_F    1048576
#define OFF_W    1572864
#define OFF_US   2097152
#define OFF_ES   2098176
#define OFF_ERR  2099200
#define OFF_CAL  2623488

// ---------------------------------------------------------------------------
// Compile-time twiddle tables in __constant__ memory.
// C[n-1][k] = cos(2*pi*n*k/256), S[n-1][k] = sin(...), n=1..63, k=0..31.
// Warp-uniform runtime index -> LDC (constant port), off the smem crossbar.
// ---------------------------------------------------------------------------
__host__ __device__ constexpr double k_cpi_taylor(double x) {  // cos(x)
    double term = 1.0, sum = 1.0, x2 = x * x;
    for (int j = 1; j <= 14; j++) { term *= -x2 / double((2*j-1)*(2*j)); sum += term; }
    return sum;
}
__host__ __device__ constexpr double k_cos256(int m) {         // cos(2*pi*m/256)
    m &= 255;
    if (m > 128) m = 256 - m;
    constexpr double PI = 3.14159265358979323846;
    if (m <= 64) return  k_cpi_taylor(PI * (double)m / 128.0);
    return -k_cpi_taylor(PI * (double)(128 - m) / 128.0);
}

struct alignas(16) TwTab { float c[63 * 32]; float s[63 * 32]; };
__host__ __device__ constexpr TwTab k_mktab() {
    TwTab t{};
    for (int n = 1; n < 64; n++)
        for (int k = 0; k < 32; k++) {
            t.c[(n - 1) * 32 + k] = (float)k_cos256(n * k);
            t.s[(n - 1) * 32 + k] = (float)k_cos256(n * k + 192);   // sin
        }
    return t;
}
__constant__ TwTab TWC = k_mktab();

// Scratch: only the tiny modes array is global.
__device__ float g_modes[(size_t)NALL * 2048];   // per image: [re 0..1023 | im 0..1023]

// ---------------------------------------------------------------------------
// K1 smem layout (floats), total 24576 fl = 98304 B -> 2 CTAs/SM:
//   CE/CO/SE/SO: r-major [32r][63n] (stride 63: conflict-free R and W)
//   BD[4][32]: boundary values (x0+x128, x0-x128, u64, v64) per row
//   sT: [c 0..63][row 0..255], XOR swizzle addr = c*256 + (row ^ (c&31))
//   sRA/sRB (stage B results) reuse the fold region: [c 0..63][k 0..31] stride 33
// ---------------------------------------------------------------------------
#define CE_OFF 0
#define CO_OFF 2016
#define SE_OFF 4032
#define SO_OFF 6048
#define BD_OFF 8064
#define OT     8192
#define K1_FLOATS 24576
#define RA 0
#define RB 2112

// ---------------------------------------------------------------------------
// Fold: load (gmem -> regs) and store (fold arith -> smem), 512 threads.
// Thread: n = tid&63, rbase = tid>>6; 4 iterations cover 32 rows.
// ---------------------------------------------------------------------------
__device__ __forceinline__ void loadA(float (&v)[16], const float* src, int tid, int q)
{
    const float* rows = src + q * 32 * 256;
    const int n = tid & 63;
    const int rbase = tid >> 6;          // 0..7
#pragma unroll
    for (int it = 0; it < 4; it++) {
        const float* row = rows + (rbase + it * 8) * 256;
        if (n == 0) {
            v[it*4+0] = row[0];   v[it*4+1] = row[128];
            v[it*4+2] = row[64];  v[it*4+3] = row[192];
        } else {
            v[it*4+0] = row[n];        v[it*4+1] = row[256 - n];
            v[it*4+2] = row[128 - n];  v[it*4+3] = row[128 + n];
        }
    }
}

__device__ __forceinline__ void storeA(float* sm, const float (&v)[16], int tid)
{
    const int n = tid & 63;
    const int rbase = tid >> 6;
#pragma unroll
    for (int it = 0; it < 4; it++) {
        const int r = rbase + it * 8;
        float a = v[it*4+0], b = v[it*4+1], e = v[it*4+2], d = v[it*4+3];
        if (n == 0) {
            sm[BD_OFF +      r] = a + b;     // x0 + x128
            sm[BD_OFF + 32 + r] = a - b;     // x0 - x128
            sm[BD_OFF + 64 + r] = e + d;     // u64
            sm[BD_OFF + 96 + r] = e - d;     // v64
        } else {
            float u1 = a + b, u2 = e + d, v1 = a - b, v2 = e - d;
            sm[CE_OFF + r * 63 + (n - 1)] = u1 + u2;
            sm[CO_OFF + r * 63 + (n - 1)] = u1 - u2;
            sm[SE_OFF + r * 63 + (n - 1)] = v1 - v2;
            sm[SO_OFF + r * 63 + (n - 1)] = v1 + v2;
        }
    }
}

// ---------------------------------------------------------------------------
// Stage A compute: warp = (HALF, j).  HALF 0 = Tc (cos table, CE/CO data),
// HALF 1 = Ts (sin table, SE/SO).  4 k per thread (k = 4j..4j+3), lane = row.
// Uniform sum: acc_k = boundary(n=0) + sum_{n=1..63} D[n]*T[n][k] + boundary(n=64).
// ---------------------------------------------------------------------------
template<int HALF>
__device__ __forceinline__ void stageA_warp(float* sm, int lane, int k0, int q)
{
    const float* dE = sm + (HALF ? SE_OFF : CE_OFF) + lane * 63;
    const float* dO = sm + (HALF ? SO_OFF : CO_OFF) + lane * 63;

    float a0, a1, a2, a3;
    if (HALF == 0) {
        float be = sm[BD_OFF + lane];        // x0 + x128 (even k, n=0)
        float bo = sm[BD_OFF + 32 + lane];   // x0 - x128 (odd k)
        a0 = be; a1 = bo; a2 = be; a3 = bo;
    } else {
        a0 = a1 = a2 = a3 = 0.f;             // sin(0) = 0
    }

#pragma unroll
    for (int n = 1; n < 64; n++) {
        float e = dE[n - 1];
        float o = dO[n - 1];
        float4 t;
        if (HALF == 0) t = *(const float4*)&TWC.c[(n - 1) * 32 + k0];
        else           t = *(const float4*)&TWC.s[(n - 1) * 32 + k0];
        a0 = fmaf(e, t.x, a0);
        a1 = fmaf(o, t.y, a1);
        a2 = fmaf(e, t.z, a2);
        a3 = fmaf(o, t.w, a3);
    }

    // n = 64 boundary: cos(pi*k/2): +1 at k=4j, -1 at k=4j+2; sin: +1 at 4j+1, -1 at 4j+3.
    if (HALF == 0) { float u = sm[BD_OFF + 64 + lane]; a0 += u; a2 -= u; }
    else           { float v = sm[BD_OFF + 96 + lane]; a1 += v; a3 -= v; }

    const int row = q * 32 + lane;
    float* sT = sm + OT + (HALF ? 32 * 256 : 0);
    sT[(k0 + 0) * 256 + (row ^ (k0 + 0))] = a0;
    sT[(k0 + 1) * 256 + (row ^ (k0 + 1))] = a1;
    sT[(k0 + 2) * 256 + (row ^ (k0 + 2))] = a2;
    sT[(k0 + 3) * 256 + (row ^ (k0 + 3))] = a3;
}

// ---------------------------------------------------------------------------
// Stage B compute: warp = (HALF, j).  HALF 0 = cos sums (A), 1 = sin sums (B).
// Thread handles columns c = lane and lane+32, k = 4j..4j+3, fold on the fly.
// ---------------------------------------------------------------------------
template<int HALF>
__device__ __forceinline__ void stageB_warp(float* sm, int lane, int k0)
{
#pragma unroll 1
    for (int cc = 0; cc < 2; cc++) {
        const int c  = lane + cc * 32;
        const int cb = c & 31;
        const float* col = sm + OT + c * 256;

        float s0   = col[0 ^ cb];
        float s64  = col[64 ^ cb];
        float s128 = col[128 ^ cb];
        float s192 = col[192 ^ cb];

        float a0, a1, a2, a3;
        if (HALF == 0) {
            float p10 = s0 + s128, p20 = s0 - s128;
            a0 = p10; a1 = p20; a2 = p10; a3 = p20;
        } else {
            a0 = a1 = a2 = a3 = 0.f;
        }

#pragma unroll
        for (int n = 1; n < 64; n++) {
            float a = col[n ^ cb];
            float b = col[(256 - n) ^ cb];
            float e = col[(128 - n) ^ cb];
            float d = col[(128 + n) ^ cb];
            float ev, od;
            float4 t;
            if (HALF == 0) {
                float u1 = a + b, u2 = e + d;
                ev = u1 + u2; od = u1 - u2;
                t = *(const float4*)&TWC.c[(n - 1) * 32 + k0];
            } else {
                float v1 = a - b, v2 = e - d;
                ev = v1 - v2; od = v1 + v2;
                t = *(const float4*)&TWC.s[(n - 1) * 32 + k0];
            }
            a0 = fmaf(ev, t.x, a0);
            a1 = fmaf(od, t.y, a1);
            a2 = fmaf(ev, t.z, a2);
            a3 = fmaf(od, t.w, a3);
        }

        if (HALF == 0) { float pe = s64 + s192; a0 += pe; a2 -= pe; }
        else           { float po = s64 - s192; a1 += po; a3 -= po; }

        float* dst = sm + (HALF ? RB : RA) + c * 33 + k0;
        dst[0] = a0; dst[1] = a1; dst[2] = a2; dst[3] = a3;
    }
}

// ---------------------------------------------------------------------------
// K1: fused rfft2.  CTA = one image, 512 threads, 98 KB smem (2 CTAs/SM).
// ---------------------------------------------------------------------------
__global__ __launch_bounds__(512, 2) void k_rfft2(const float* __restrict__ pred,
                                                  const float* __restrict__ gt)
{
    extern __shared__ float sm[];

    const int img = blockIdx.x;
    const float* src = (img < NIMG) ? pred + (size_t)img * 65536
                                    : gt   + (size_t)(img - NIMG) * 65536;
    const int tid  = threadIdx.x;
    const int wid  = tid >> 5;
    const int lane = tid & 31;
    const int half = wid >> 3;          // 0: cos-group, 1: sin-group
    const int k0   = (wid & 7) * 4;

    float v[16];
    loadA(v, src, tid, 0);

#pragma unroll 1
    for (int q = 0; q < 8; q++) {
        storeA(sm, v, tid);
        __syncthreads();
        if (q < 7) loadA(v, src, tid, q + 1);   // overlap with compute
        if (half == 0) stageA_warp<0>(sm, lane, k0, q);
        else           stageA_warp<1>(sm, lane, k0, q);
        __syncthreads();                        // fold buffers reusable next q
    }

    // Stage B: column DFT of sT, results into fold region (sRA/sRB).
    if (half == 0) stageB_warp<0>(sm, lane, k0);
    else           stageB_warp<1>(sm, lane, k0);
    __syncthreads();

    // Combine partials into complex modes; coalesced writes.
    float* mp = g_modes + (size_t)img * 2048;
#pragma unroll
    for (int t = 0; t < 2; t++) {
        int idx = tid + t * 512;
        int k1 = idx >> 5, k2 = idx & 31;
        float ATc = sm[RA + k2 * 33 + k1];
        float ATs = sm[RA + (32 + k2) * 33 + k1];
        float BTc = sm[RB + k2 * 33 + k1];
        float BTs = sm[RB + (32 + k2) * 33 + k1];
        mp[idx]        = ATc - BTs;
        mp[1024 + idx] = -(BTc + ATs);
    }
}

// ---------------------------------------------------------------------------
// K2: fused MLP + epilogue (unchanged, known-good).
// ---------------------------------------------------------------------------
__global__ __launch_bounds__(256) void k_mlp_epi(const float* __restrict__ W1,
                                                 const float* __restrict__ b1,
                                                 const float* __restrict__ W2,
                                                 const float* __restrict__ b2,
                                                 const float* __restrict__ W3,
                                                 const float* __restrict__ b3,
                                                 float* __restrict__ out)
{
    __shared__ float sW1[128], sb1[64], sW2[2048], sb2[32], sW3[32], sb3v;
    __shared__ float sRed[256];
    __shared__ float sTe;
    const int tid = threadIdx.x;
    const int img = blockIdx.x;

    for (int i = tid; i < 128;  i += 256) sW1[i] = W1[i];
    for (int i = tid; i < 2048; i += 256) sW2[i] = W2[i];
    if (tid < 64) sb1[tid] = b1[tid];
    if (tid < 32) { sb2[tid] = b2[tid]; sW3[tid] = W3[tid]; }
    if (tid == 0) sb3v = b3[0];
    __syncthreads();

    const float* mp = g_modes + (size_t)img * 2048;
    const float* mg = g_modes + (size_t)(NIMG + img) * 2048;
    const int base = img * 1024;

    float ev[4], uv[4];
    float eSum = 0.f;

#pragma unroll 1
    for (int bi = 0; bi < 2; bi++) {
        const int i0 = tid + bi * 512;
        const int i1 = i0 + 256;
        float pr0 = mp[i0], pi0 = mp[1024 + i0];
        float pr1 = mp[i1], pi1 = mp[1024 + i1];
        float gr0 = mg[i0], gi0 = mg[1024 + i0];
        float gr1 = mg[i1], gi1 = mg[1024 + i1];

        float E0 = fmaf(pr0, pr0, pi0 * pi0);
        float E1 = fmaf(pr1, pr1, pi1 * pi1);
        out[OFF_E + base + i0] = E0;
        out[OFF_E + base + i1] = E1;
        float d0r = pr0 - gr0, d0i = pi0 - gi0;
        float d1r = pr1 - gr1, d1i = pi1 - gi1;
        out[OFF_ERR + base + i0] = fmaf(d0r, d0r, d0i * d0i);
        out[OFF_ERR + base + i1] = fmaf(d1r, d1r, d1i * d1i);
        ev[bi * 2] = E0; ev[bi * 2 + 1] = E1;
        eSum += E0 + E1;

        float h2a[32], h2b[32];
#pragma unroll
        for (int j = 0; j < 32; j++) { h2a[j] = sb2[j]; h2b[j] = sb2[j]; }

#pragma unroll 8
        for (int i = 0; i < 64; i++) {
            float w1a = sW1[i], w1b = sW1[64 + i], bb = sb1[i];
            float a0 = fmaf(pr0, w1a, fmaf(pi0, w1b, bb));
            float a1 = fmaf(pr1, w1a, fmaf(pi1, w1b, bb));
            a0 = a0 > 0.f ? a0 : 0.f;
            a1 = a1 > 0.f ? a1 : 0.f;
            const float4* w4 = (const float4*)(sW2 + i * 32);
#pragma unroll
            for (int qq = 0; qq < 8; qq++) {
                float4 w = w4[qq];
                h2a[qq*4+0] = fmaf(a0, w.x, h2a[qq*4+0]);
                h2a[qq*4+1] = fmaf(a0, w.y, h2a[qq*4+1]);
                h2a[qq*4+2] = fmaf(a0, w.z, h2a[qq*4+2]);
                h2a[qq*4+3] = fmaf(a0, w.w, h2a[qq*4+3]);
                h2b[qq*4+0] = fmaf(a1, w.x, h2b[qq*4+0]);
                h2b[qq*4+1] = fmaf(a1, w.y, h2b[qq*4+1]);
                h2b[qq*4+2] = fmaf(a1, w.z, h2b[qq*4+2]);
                h2b[qq*4+3] = fmaf(a1, w.w, h2b[qq*4+3]);
            }
        }
        float o0 = sb3v, o1 = sb3v;
#pragma unroll
        for (int j = 0; j < 32; j++) {
            float va = h2a[j] > 0.f ? h2a[j] : 0.f;
            float vb = h2b[j] > 0.f ? h2b[j] : 0.f;
            o0 = fmaf(va, sW3[j], o0);
            o1 = fmaf(vb, sW3[j], o1);
        }
        float u0 = fmaxf(o0, 0.f) + log1pf(expf(-fabsf(o0)));
        float u1 = fmaxf(o1, 0.f) + log1pf(expf(-fabsf(o1)));
        out[OFF_U + base + i0] = u0;
        out[OFF_U + base + i1] = u1;
        uv[bi * 2] = u0; uv[bi * 2 + 1] = u1;
    }

    sRed[tid] = eSum;
    __syncthreads();
    for (int w = 128; w > 0; w >>= 1) {
        if (tid < w) sRed[tid] += sRed[tid + w];
        __syncthreads();
    }
    if (tid == 0) sTe = sRed[0];
    __syncthreads();
    const float te = sTe + 1e-8f;

#pragma unroll
    for (int b = 0; b < 4; b++) {
        int idx = tid + b * 256;
        float F = ev[b] / te;
        out[OFF_F + base + idx] = F;
        out[OFF_W + base + idx] = F * uv[b];
    }
}

// ---------------------------------------------------------------------------
// K3: per-mode stats (unchanged, known-good).
// ---------------------------------------------------------------------------
__global__ __launch_bounds__(256) void k_stats(float* __restrict__ out)
{
    __shared__ double red[6][256];
    const int tid = threadIdx.x;
    const int kl  = tid & 7;
    const int sg  = tid >> 3;                 // 0..31
    const int k   = blockIdx.x * 8 + kl;

    double su = 0, se = 0, sen = 0, sue = 0, suu = 0, see = 0;
    for (int s = sg; s < NIMG; s += 32) {
        float u  = out[OFF_U   + (size_t)s * 1024 + k];
        float e  = out[OFF_ERR + (size_t)s * 1024 + k];
        float en = out[OFF_E   + (size_t)s * 1024 + k];
        su += u; se += e; sen += en;
        sue += (double)u * (double)e;
        suu += (double)u * (double)u;
        see += (double)e * (double)e;
    }
    red[0][tid] = su;  red[1][tid] = se;  red[2][tid] = sen;
    red[3][tid] = sue; red[4][tid] = suu; red[5][tid] = see;
    __syncthreads();

    for (int off = 16; off >= 1; off >>= 1) {
        if (sg < off) {
#pragma unroll
            for (int m = 0; m < 6; m++)
                red[m][tid] += red[m][tid + off * 8];
        }
        __syncthreads();
    }
    if (tid < 8) {
        double tsu = red[0][tid], tse = red[1][tid], tsen = red[2][tid];
        double tsue = red[3][tid], tsuu = red[4][tid], tsee = red[5][tid];
        out[OFF_US + k] = (float)(tsu  * (1.0 / 512.0));
        out[OFF_ES + k] = (float)(tsen * (1.0 / 512.0));
        double num  = tsue - tsu * tse * (1.0 / 512.0);
        double varu = tsuu - tsu * tsu * (1.0 / 512.0);
        double vare = tsee - tse * tse * (1.0 / 512.0);
        out[OFF_CAL + k] = (float)(num / (sqrt(varu * vare) + 1e-8));
    }
}

// ---------------------------------------------------------------------------
extern "C" void kernel_launch(void* const* d_in, const int* in_sizes, int n_in,
                              void* d_out, int out_size)
{
    const float* pred = (const float*)d_in[0];
    // d_in[1] = uncertainty: unused by the reference
    const float* gt   = (const float*)d_in[2];
    const float* W1   = (const float*)d_in[3];
    const float* b1   = (const float*)d_in[4];
    const float* W2   = (const float*)d_in[5];
    const float* b2   = (const float*)d_in[6];
    const float* W3   = (const float*)d_in[7];
    const float* b3   = (const float*)d_in[8];
    float* out = (float*)d_out;

    const int smem1 = K1_FLOATS * 4;   // 98304 B
    cudaFuncSetAttribute(k_rfft2, cudaFuncAttributeMaxDynamicSharedMemorySize, smem1);

    k_rfft2<<<1024, 512, smem1>>>(pred, gt);
    k_mlp_epi<<<512, 256>>>(W1, b1, W2, b2, W3, b3, out);
    k_stats<<<128, 256>>>(out);
}

// round 13
// speedup vs baseline: 1.6090x; 1.6090x over previous
#include <cuda_runtime.h>
#include <math.h>

// Problem constants
#define NIMG 512          // B*C
#define NALL 1024         // pred + gt images

// Output offsets (tuple order, flattened)
#define OFF_E    0
#define OFF_U    524288
#define OFF_F    1048576
#define OFF_W    1572864
#define OFF_US   2097152
#define OFF_ES   2098176
#define OFF_ERR  2099200
#define OFF_CAL  2623488

// ---------------------------------------------------------------------------
// Compile-time twiddles -> FFMA immediates (template-parameter constexpr).
// ---------------------------------------------------------------------------
__host__ __device__ constexpr double k_cpi_taylor(double x) {  // cos(x)
    double term = 1.0, sum = 1.0, x2 = x * x;
    for (int j = 1; j <= 14; j++) { term *= -x2 / double((2*j-1)*(2*j)); sum += term; }
    return sum;
}
__host__ __device__ constexpr double k_cos256(int m) {         // cos(2*pi*m/256)
    m &= 255;
    if (m > 128) m = 256 - m;
    constexpr double PI = 3.14159265358979323846;
    if (m <= 64) return  k_cpi_taylor(PI * (double)m / 128.0);
    return -k_cpi_taylor(PI * (double)(128 - m) / 128.0);
}

// Scratch: only the tiny modes array is global.
__device__ float g_modes[(size_t)NALL * 2048];   // per image: [re 0..1023 | im 0..1023]

// ---------------------------------------------------------------------------
// Packed fp32x2 helpers (base sm_100 ISA; SASS FFMA2).  Bit-exact: two
// independent IEEE fp32 FMAs per instruction.
// ---------------------------------------------------------------------------
typedef unsigned long long u64p;
static __device__ __forceinline__ u64p pk2(float x, float y) {
    u64p r; asm("mov.b64 %0, {%1, %2};" : "=l"(r) : "f"(x), "f"(y)); return r;
}
static __device__ __forceinline__ u64p dup2(float x) {
    u64p r; asm("mov.b64 %0, {%1, %1};" : "=l"(r) : "f"(x)); return r;
}
static __device__ __forceinline__ void unpk2(u64p p, float& x, float& y) {
    asm("mov.b64 {%0, %1}, %2;" : "=f"(x), "=f"(y) : "l"(p));
}
static __device__ __forceinline__ u64p fma2(u64p a, u64p b, u64p c) {
    u64p d; asm("fma.rn.f32x2 %0, %1, %2, %3;" : "=l"(d) : "l"(a), "l"(b), "l"(c));
    return d;
}

// ---------------------------------------------------------------------------
// K1 smem layout (floats) — identical to the R7-passing (405us) kernel:
//   fold buffers: 4 x [n 0..63][r 0..31] stride 33
//   sT: [c 0..63][row 0..255], XOR swizzle addr = c*256 + (row ^ (c&31))
//   sRA/sRB (stage B results, reuse fold area): [c][k1] stride 33
// ---------------------------------------------------------------------------
#define F_CE 0
#define F_CO 2112
#define F_SE 4224
#define F_SO 6336
#define OT   8448
#define K1_FLOATS 24832          // 99328 bytes -> 2 CTAs/SM
#define RA 0
#define RB 2112

// ---------------------------------------------------------------------------
// Stage A inner machinery: literal-twiddle FMA steps via template recursion.
// ---------------------------------------------------------------------------
template<int P, int JG, int N, int JJ> struct FmaJ {
    static __device__ __forceinline__ void f(float cu, float sv,
                                             float (&aC)[4], float (&aS)[4]) {
        constexpr int   K  = 2 * (JG * 4 + JJ) + P;
        constexpr float cc = (float)k_cos256(N * K);
        aC[JJ] = fmaf(cu, cc, aC[JJ]);
        if constexpr (K > 0) {
            constexpr float ss = (float)k_cos256(N * K + 192);   // sin
            aS[JJ] = fmaf(sv, ss, aS[JJ]);
        }
    }
};

template<int P, int JG, int N> struct AStep {
    static __device__ __forceinline__ void run(const float* fc, const float* fs, int lane,
                                               float (&aC)[4], float (&aS)[4]) {
        const float cu = fc[N * 33 + lane];
        const float sv = fs[N * 33 + lane];
        FmaJ<P, JG, N, 0>::f(cu, sv, aC, aS);
        FmaJ<P, JG, N, 1>::f(cu, sv, aC, aS);
        FmaJ<P, JG, N, 2>::f(cu, sv, aC, aS);
        FmaJ<P, JG, N, 3>::f(cu, sv, aC, aS);
        AStep<P, JG, N + 1>::run(fc, fs, lane, aC, aS);
    }
};
template<int P, int JG> struct AStep<P, JG, 64> {
    static __device__ __forceinline__ void run(const float*, const float*, int,
                                               float (&)[4], float (&)[4]) {}
};

// Stage A compute: warp = (parity P, j-group JG); thread = row lane.
template<int P, int JG>
__device__ __forceinline__ void stageA_compute(const float* sm, float* sT, int lane, int q)
{
    const float* fc = sm + (P ? F_CO : F_CE);
    const float* fs = sm + (P ? F_SO : F_SE);
    float accC[4] = {0.f, 0.f, 0.f, 0.f};
    float accS[4] = {0.f, 0.f, 0.f, 0.f};

    AStep<P, JG, 1>::run(fc, fs, lane, accC, accS);

    float x0 = sm[F_CE + lane], x128 = sm[F_CO + lane];
    float u64v = sm[F_SE + lane], v64v = sm[F_SO + lane];
#pragma unroll
    for (int jj = 0; jj < 4; jj++) {
        const int j = JG * 4 + jj;
        if (P == 0) {
            accC[jj] += x0 + x128 + ((j & 1) ? -u64v : u64v);
        } else {
            accC[jj] += x0 - x128;
            accS[jj] += (j & 1) ? -v64v : v64v;
        }
    }
    const int row = q * 32 + lane;
#pragma unroll
    for (int jj = 0; jj < 4; jj++) {
        const int k = 2 * (JG * 4 + jj) + P;
        sT[k * 256 + (row ^ (k & 31))]        = accC[jj];
        sT[(32 + k) * 256 + (row ^ (k & 31))] = accS[jj];
    }
}

// ---------------------------------------------------------------------------
// Stage B inner machinery (same literal-twiddle trick).
// ---------------------------------------------------------------------------
template<int P, int JH, int N, int JJ> struct BFma {
    static __device__ __forceinline__ void f(float cs, float ss,
                                             float (&aA)[8], float (&aB)[8]) {
        constexpr int   K  = 2 * (JH * 8 + JJ) + P;
        constexpr float cc = (float)k_cos256(N * K);
        aA[JJ] = fmaf(cs, cc, aA[JJ]);
        if constexpr (K > 0) {
            constexpr float sn = (float)k_cos256(N * K + 192);
            aB[JJ] = fmaf(ss, sn, aB[JJ]);
        }
    }
};

template<int P, int JH, int N> struct BStep {
    static __device__ __forceinline__ void run(const float* col, int cb,
                                               float (&aA)[8], float (&aB)[8]) {
        float a = col[N ^ cb];
        float b = col[(256 - N) ^ cb];
        float e = col[(128 - N) ^ cb];
        float d = col[(128 + N) ^ cb];
        float cs, ss;
        if constexpr (P == 0) { cs = (a + b) + (e + d); ss = (a - b) - (e - d); }
        else                  { cs = (a + b) - (e + d); ss = (a - b) + (e - d); }
        BFma<P, JH, N, 0>::f(cs, ss, aA, aB);
        BFma<P, JH, N, 1>::f(cs, ss, aA, aB);
        BFma<P, JH, N, 2>::f(cs, ss, aA, aB);
        BFma<P, JH, N, 3>::f(cs, ss, aA, aB);
        BFma<P, JH, N, 4>::f(cs, ss, aA, aB);
        BFma<P, JH, N, 5>::f(cs, ss, aA, aB);
        BFma<P, JH, N, 6>::f(cs, ss, aA, aB);
        BFma<P, JH, N, 7>::f(cs, ss, aA, aB);
        BStep<P, JH, N + 1>::run(col, cb, aA, aB);
    }
};
template<int P, int JH> struct BStep<P, JH, 64> {
    static __device__ __forceinline__ void run(const float*, int,
                                               float (&)[8], float (&)[8]) {}
};

template<int P, int JH>
__device__ __forceinline__ void stageB_compute(const float* sT, float* sm, int c)
{
    const int cb = c & 31;
    const float* col = sT + c * 256;
    float aA[8] = {0.f,0.f,0.f,0.f,0.f,0.f,0.f,0.f};
    float aB[8] = {0.f,0.f,0.f,0.f,0.f,0.f,0.f,0.f};

    BStep<P, JH, 1>::run(col, cb, aA, aB);

    float s0 = col[0 ^ cb], s64 = col[64 ^ cb];
    float s128 = col[128 ^ cb], s192 = col[192 ^ cb];
#pragma unroll
    for (int jj = 0; jj < 8; jj++) {
        const int j = JH * 8 + jj;
        const int k = 2 * j + P;
        if (P == 0) {
            float pe = s64 + s192;
            aA[jj] += s0 + s128 + ((j & 1) ? -pe : pe);
        } else {
            float po = s64 - s192;
            aA[jj] += s0 - s128;
            aB[jj] += (j & 1) ? -po : po;
        }
        sm[RA + c * 33 + k] = aA[jj];
        sm[RB + c * 33 + k] = aB[jj];
    }
}

// ---------------------------------------------------------------------------
// Fold phase split into load (gmem -> regs) and store (fold arith -> smem)
// so chunk q+1's loads overlap chunk q's compute.
// ---------------------------------------------------------------------------
__device__ __forceinline__ void loadA(float (&v)[32], const float* src, int tid, int q)
{
    const float* rows = src + q * 32 * 256;
    const int n = tid & 63;
    const int rbase = tid >> 6;
#pragma unroll
    for (int it = 0; it < 8; it++) {
        const float* row = rows + (rbase + it * 4) * 256;
        if (n == 0) {
            v[it*4+0] = row[0];   v[it*4+1] = row[128];
            v[it*4+2] = row[64];  v[it*4+3] = row[192];
        } else {
            v[it*4+0] = row[n];        v[it*4+1] = row[256 - n];
            v[it*4+2] = row[128 - n];  v[it*4+3] = row[128 + n];
        }
    }
}

__device__ __forceinline__ void storeA(float* sm, const float (&v)[32], int tid)
{
    const int n = tid & 63;
    const int rbase = tid >> 6;
#pragma unroll
    for (int it = 0; it < 8; it++) {
        const int r = rbase + it * 4;
        float a = v[it*4+0], b = v[it*4+1], e = v[it*4+2], d = v[it*4+3];
        if (n == 0) {
            sm[F_CE + r] = a;
            sm[F_CO + r] = b;
            sm[F_SE + r] = e + d;
            sm[F_SO + r] = e - d;
        } else {
            sm[F_CE + n * 33 + r] = (a + b) + (e + d);
            sm[F_CO + n * 33 + r] = (a + b) - (e + d);
            sm[F_SE + n * 33 + r] = (a - b) - (e - d);
            sm[F_SO + n * 33 + r] = (a - b) + (e - d);
        }
    }
}

// ---------------------------------------------------------------------------
// K1: fused rfft2.  CTA = one image.  Pipelined stage A + in-smem stage B.
// (Verbatim the R7 405us-passing kernel.)
// ---------------------------------------------------------------------------
__global__ __launch_bounds__(256) void k_rfft2(const float* __restrict__ pred,
                                               const float* __restrict__ gt)
{
    extern __shared__ float sm[];
    float* sT = sm + OT;

    const int img = blockIdx.x;
    const float* src = (img < NIMG) ? pred + (size_t)img * 65536
                                    : gt   + (size_t)(img - NIMG) * 65536;
    const int tid  = threadIdx.x;
    const int wid  = tid >> 5;
    const int lane = tid & 31;

    float v[32];
    loadA(v, src, tid, 0);

#pragma unroll 1
    for (int q = 0; q < 8; q++) {
        storeA(sm, v, tid);
        __syncthreads();
        if (q < 7) loadA(v, src, tid, q + 1);   // overlap with compute below
        switch (wid) {
            case 0: stageA_compute<0, 0>(sm, sT, lane, q); break;
            case 1: stageA_compute<1, 0>(sm, sT, lane, q); break;
            case 2: stageA_compute<0, 1>(sm, sT, lane, q); break;
            case 3: stageA_compute<1, 1>(sm, sT, lane, q); break;
            case 4: stageA_compute<0, 2>(sm, sT, lane, q); break;
            case 5: stageA_compute<1, 2>(sm, sT, lane, q); break;
            case 6: stageA_compute<0, 3>(sm, sT, lane, q); break;
            case 7: stageA_compute<1, 3>(sm, sT, lane, q); break;
        }
        __syncthreads();
    }

    // Stage B: fold-on-the-fly column DFT of sT (results into fold area).
    {
        const int c = (wid >> 2) * 32 + lane;
        switch (wid & 3) {
            case 0: stageB_compute<0, 0>(sT, sm, c); break;
            case 1: stageB_compute<1, 0>(sT, sm, c); break;
            case 2: stageB_compute<0, 1>(sT, sm, c); break;
            case 3: stageB_compute<1, 1>(sT, sm, c); break;
        }
    }
    __syncthreads();

    // Combine partials into complex modes; coalesced writes.
    float* mp = g_modes + (size_t)img * 2048;
#pragma unroll
    for (int t = 0; t < 4; t++) {
        int idx = tid + t * 256;
        int k1 = idx >> 5, k2 = idx & 31;
        float ATc = sm[RA + k2 * 33 + k1];
        float ATs = sm[RA + (32 + k2) * 33 + k1];
        float BTc = sm[RB + k2 * 33 + k1];
        float BTs = sm[RB + (32 + k2) * 33 + k1];
        mp[idx]        = ATc - BTs;
        mp[1024 + idx] = -(BTc + ATs);
    }
}

// ---------------------------------------------------------------------------
// K2: fused MLP + epilogue.  Inner 64x32 loop packed with fma.rn.f32x2
// (FFMA2): bit-exact, ~40% fewer issues, FMA-pipe slots halved.
// ---------------------------------------------------------------------------
__global__ __launch_bounds__(256) void k_mlp_epi(const float* __restrict__ W1,
                                                 const float* __restrict__ b1,
                                                 const float* __restrict__ W2,
                                                 const float* __restrict__ b2,
                                                 const float* __restrict__ W3,
                                                 const float* __restrict__ b3,
                                                 float* __restrict__ out)
{
    __shared__ float sW1[128], sb1[64], sb2[32], sW3[32], sb3v;
    __shared__ __align__(16) float sW2[2048];
    __shared__ float sRed[256];
    __shared__ float sTe;
    const int tid = threadIdx.x;
    const int img = blockIdx.x;

    for (int i = tid; i < 128;  i += 256) sW1[i] = W1[i];
    for (int i = tid; i < 2048; i += 256) sW2[i] = W2[i];
    if (tid < 64) sb1[tid] = b1[tid];
    if (tid < 32) { sb2[tid] = b2[tid]; sW3[tid] = W3[tid]; }
    if (tid == 0) sb3v = b3[0];
    __syncthreads();

    const float* mp = g_modes + (size_t)img * 2048;
    const float* mg = g_modes + (size_t)(NIMG + img) * 2048;
    const int base = img * 1024;

    float ev[4], uv[4];
    float eSum = 0.f;

#pragma unroll 1
    for (int bi = 0; bi < 2; bi++) {
        const int i0 = tid + bi * 512;
        const int i1 = i0 + 256;
        float pr0 = mp[i0], pi0 = mp[1024 + i0];
        float pr1 = mp[i1], pi1 = mp[1024 + i1];
        float gr0 = mg[i0], gi0 = mg[1024 + i0];
        float gr1 = mg[i1], gi1 = mg[1024 + i1];

        float E0 = fmaf(pr0, pr0, pi0 * pi0);
        float E1 = fmaf(pr1, pr1, pi1 * pi1);
        out[OFF_E + base + i0] = E0;
        out[OFF_E + base + i1] = E1;
        float d0r = pr0 - gr0, d0i = pi0 - gi0;
        float d1r = pr1 - gr1, d1i = pi1 - gi1;
        out[OFF_ERR + base + i0] = fmaf(d0r, d0r, d0i * d0i);
        out[OFF_ERR + base + i1] = fmaf(d1r, d1r, d1i * d1i);
        ev[bi * 2] = E0; ev[bi * 2 + 1] = E1;
        eSum += E0 + E1;

        // Packed accumulators: 16 f32x2 pairs per mode = 32 h2 values.
        u64p h2a2[16], h2b2[16];
#pragma unroll
        for (int q = 0; q < 16; q++) {
            u64p b2p = pk2(sb2[2 * q], sb2[2 * q + 1]);
            h2a2[q] = b2p;
            h2b2[q] = b2p;
        }

#pragma unroll 8
        for (int i = 0; i < 64; i++) {
            float w1a = sW1[i], w1b = sW1[64 + i], bb = sb1[i];
            float a0 = fmaf(pr0, w1a, fmaf(pi0, w1b, bb));
            float a1 = fmaf(pr1, w1a, fmaf(pi1, w1b, bb));
            a0 = a0 > 0.f ? a0 : 0.f;
            a1 = a1 > 0.f ? a1 : 0.f;
            u64p a0p = dup2(a0);
            u64p a1p = dup2(a1);
            const ulonglong2* w2p = (const ulonglong2*)(sW2 + i * 32);
#pragma unroll
            for (int q = 0; q < 8; q++) {
                ulonglong2 wp = w2p[q];          // 4 consecutive W2 floats
                h2a2[2*q]   = fma2(a0p, wp.x, h2a2[2*q]);
                h2a2[2*q+1] = fma2(a0p, wp.y, h2a2[2*q+1]);
                h2b2[2*q]   = fma2(a1p, wp.x, h2b2[2*q]);
                h2b2[2*q+1] = fma2(a1p, wp.y, h2b2[2*q+1]);
            }
        }
        float o0 = sb3v, o1 = sb3v;
#pragma unroll
        for (int q = 0; q < 16; q++) {
            float xa, ya, xb, yb;
            unpk2(h2a2[q], xa, ya);
            unpk2(h2b2[q], xb, yb);
            float w3x = sW3[2 * q], w3y = sW3[2 * q + 1];
            o0 = fmaf(xa > 0.f ? xa : 0.f, w3x, o0);
            o0 = fmaf(ya > 0.f ? ya : 0.f, w3y, o0);
            o1 = fmaf(xb > 0.f ? xb : 0.f, w3x, o1);
            o1 = fmaf(yb > 0.f ? yb : 0.f, w3y, o1);
        }
        float u0 = fmaxf(o0, 0.f) + log1pf(expf(-fabsf(o0)));
        float u1 = fmaxf(o1, 0.f) + log1pf(expf(-fabsf(o1)));
        out[OFF_U + base + i0] = u0;
        out[OFF_U + base + i1] = u1;
        uv[bi * 2] = u0; uv[bi * 2 + 1] = u1;
    }

    sRed[tid] = eSum;
    __syncthreads();
    for (int w = 128; w > 0; w >>= 1) {
        if (tid < w) sRed[tid] += sRed[tid + w];
        __syncthreads();
    }
    if (tid == 0) sTe = sRed[0];
    __syncthreads();
    const float te = sTe + 1e-8f;

#pragma unroll
    for (int b = 0; b < 4; b++) {
        int idx = tid + b * 256;
        float F = ev[b] / te;
        out[OFF_F + base + idx] = F;
        out[OFF_W + base + idx] = F * uv[b];
    }
}

// ---------------------------------------------------------------------------
// K3: per-mode stats (unchanged, known-good).
// ---------------------------------------------------------------------------
__global__ __launch_bounds__(256) void k_stats(float* __restrict__ out)
{
    __shared__ double red[6][256];
    const int tid = threadIdx.x;
    const int kl  = tid & 7;
    const int sg  = tid >> 3;                 // 0..31
    const int k   = blockIdx.x * 8 + kl;

    double su = 0, se = 0, sen = 0, sue = 0, suu = 0, see = 0;
    for (int s = sg; s < NIMG; s += 32) {
        float u  = out[OFF_U   + (size_t)s * 1024 + k];
        float e  = out[OFF_ERR + (size_t)s * 1024 + k];
        float en = out[OFF_E   + (size_t)s * 1024 + k];
        su += u; se += e; sen += en;
        sue += (double)u * (double)e;
        suu += (double)u * (double)u;
        see += (double)e * (double)e;
    }
    red[0][tid] = su;  red[1][tid] = se;  red[2][tid] = sen;
    red[3][tid] = sue; red[4][tid] = suu; red[5][tid] = see;
    __syncthreads();

    for (int off = 16; off >= 1; off >>= 1) {
        if (sg < off) {
#pragma unroll
            for (int m = 0; m < 6; m++)
                red[m][tid] += red[m][tid + off * 8];
        }
        __syncthreads();
    }
    if (tid < 8) {
        double tsu = red[0][tid], tse = red[1][tid], tsen = red[2][tid];
        double tsue = red[3][tid], tsuu = red[4][tid], tsee = red[5][tid];
        out[OFF_US + k] = (float)(tsu  * (1.0 / 512.0));
        out[OFF_ES + k] = (float)(tsen * (1.0 / 512.0));
        double num  = tsue - tsu * tse * (1.0 / 512.0);
        double varu = tsuu - tsu * tsu * (1.0 / 512.0);
        double vare = tsee - tse * tse * (1.0 / 512.0);
        out[OFF_CAL + k] = (float)(num / (sqrt(varu * vare) + 1e-8));
    }
}

// ---------------------------------------------------------------------------
extern "C" void kernel_launch(void* const* d_in, const int* in_sizes, int n_in,
                              void* d_out, int out_size)
{
    const float* pred = (const float*)d_in[0];
    // d_in[1] = uncertainty: unused by the reference
    const float* gt   = (const float*)d_in[2];
    const float* W1   = (const float*)d_in[3];
    const float* b1   = (const float*)d_in[4];
    const float* W2   = (const float*)d_in[5];
    const float* b2   = (const float*)d_in[6];
    const float* W3   = (const float*)d_in[7];
    const float* b3   = (const float*)d_in[8];
    float* out = (float*)d_out;

    const int smem1 = K1_FLOATS * 4;   // 99328 B
    cudaFuncSetAttribute(k_rfft2, cudaFuncAttributeMaxDynamicSharedMemorySize, smem1);

    k_rfft2<<<1024, 256, smem1>>>(pred, gt);
    k_mlp_epi<<<512, 256>>>(W1, b1, W2, b2, W3, b3, out);
    k_stats<<<128, 256>>>(out);
}

// round 14
// speedup vs baseline: 1.6562x; 1.0293x over previous
#include <cuda_runtime.h>
#include <math.h>

// Problem constants
#define NIMG 512          // B*C
#define NALL 1024         // pred + gt images

// Output offsets (tuple order, flattened)
#define OFF_E    0
#define OFF_U    524288
#define OFF_F    1048576
#define OFF_W    1572864
#define OFF_US   2097152
#define OFF_ES   2098176
#define OFF_ERR  2099200
#define OFF_CAL  2623488

// ---------------------------------------------------------------------------
// Compile-time twiddles -> FFMA immediates (template-parameter constexpr).
// ---------------------------------------------------------------------------
__host__ __device__ constexpr double k_cpi_taylor(double x) {  // cos(x)
    double term = 1.0, sum = 1.0, x2 = x * x;
    for (int j = 1; j <= 14; j++) { term *= -x2 / double((2*j-1)*(2*j)); sum += term; }
    return sum;
}
__host__ __device__ constexpr double k_cos256(int m) {         // cos(2*pi*m/256)
    m &= 255;
    if (m > 128) m = 256 - m;
    constexpr double PI = 3.14159265358979323846;
    if (m <= 64) return  k_cpi_taylor(PI * (double)m / 128.0);
    return -k_cpi_taylor(PI * (double)(128 - m) / 128.0);
}

// Scratch: only the tiny modes array is global.
__device__ float g_modes[(size_t)NALL * 2048];   // per image: [re 0..1023 | im 0..1023]

// ---------------------------------------------------------------------------
// Packed fp32x2 helpers (base sm_100 ISA; SASS FFMA2).
// ---------------------------------------------------------------------------
typedef unsigned long long u64p;
static __device__ __forceinline__ u64p pk2(float x, float y) {
    u64p r; asm("mov.b64 %0, {%1, %2};" : "=l"(r) : "f"(x), "f"(y)); return r;
}
static __device__ __forceinline__ u64p dup2(float x) {
    u64p r; asm("mov.b64 %0, {%1, %1};" : "=l"(r) : "f"(x)); return r;
}
static __device__ __forceinline__ void unpk2(u64p p, float& x, float& y) {
    asm("mov.b64 {%0, %1}, %2;" : "=f"(x), "=f"(y) : "l"(p));
}
static __device__ __forceinline__ u64p fma2(u64p a, u64p b, u64p c) {
    u64p d; asm("fma.rn.f32x2 %0, %1, %2, %3;" : "=l"(d) : "l"(a), "l"(b), "l"(c));
    return d;
}

// ---------------------------------------------------------------------------
// K1 smem layout (floats) — identical to the R7/R13-passing kernel:
//   fold buffers: 4 x [n 0..63][r 0..31] stride 33
//   sT: [c 0..63][row 0..255], XOR swizzle addr = c*256 + (row ^ (c&31))
//   sRA/sRB (stage B results, reuse fold area): [c][k1] stride 33
// ---------------------------------------------------------------------------
#define F_CE 0
#define F_CO 2112
#define F_SE 4224
#define F_SO 6336
#define OT   8448
#define K1_FLOATS 24832          // 99328 bytes -> 2 CTAs/SM
#define RA 0
#define RB 2112

// ---------------------------------------------------------------------------
// Stage A inner machinery: literal-twiddle FMAs, batched loads (8 n / group)
// so 16 independent LDS issue before the 64 FMAs that consume them.
// ---------------------------------------------------------------------------
template<int P, int JG, int N, int JJ> struct FmaJ {
    static __device__ __forceinline__ void f(float cu, float sv,
                                             float (&aC)[4], float (&aS)[4]) {
        constexpr int   K  = 2 * (JG * 4 + JJ) + P;
        constexpr float cc = (float)k_cos256(N * K);
        aC[JJ] = fmaf(cu, cc, aC[JJ]);
        if constexpr (K > 0) {
            constexpr float ss = (float)k_cos256(N * K + 192);   // sin
            aS[JJ] = fmaf(sv, ss, aS[JJ]);
        }
    }
};

template<int P, int JG, int N0, int CNT, int T> struct AGg {
    static __device__ __forceinline__ void f(const float* cu, const float* sv,
                                             float (&aC)[4], float (&aS)[4]) {
        FmaJ<P, JG, N0 + T, 0>::f(cu[T], sv[T], aC, aS);
        FmaJ<P, JG, N0 + T, 1>::f(cu[T], sv[T], aC, aS);
        FmaJ<P, JG, N0 + T, 2>::f(cu[T], sv[T], aC, aS);
        FmaJ<P, JG, N0 + T, 3>::f(cu[T], sv[T], aC, aS);
        AGg<P, JG, N0, CNT, T + 1>::f(cu, sv, aC, aS);
    }
};
template<int P, int JG, int N0, int CNT> struct AGg<P, JG, N0, CNT, CNT> {
    static __device__ __forceinline__ void f(const float*, const float*,
                                             float (&)[4], float (&)[4]) {}
};

template<int P, int JG, int N0> struct AChain {
    static constexpr int CNT = (64 - N0) < 8 ? (64 - N0) : 8;
    static __device__ __forceinline__ void run(const float* fc, const float* fs, int lane,
                                               float (&aC)[4], float (&aS)[4]) {
        float cu[CNT], sv[CNT];
#pragma unroll
        for (int t = 0; t < CNT; t++) {
            cu[t] = fc[(N0 + t) * 33 + lane];
            sv[t] = fs[(N0 + t) * 33 + lane];
        }
        AGg<P, JG, N0, CNT, 0>::f(cu, sv, aC, aS);
        AChain<P, JG, N0 + CNT>::run(fc, fs, lane, aC, aS);
    }
};
template<int P, int JG> struct AChain<P, JG, 64> {
    static __device__ __forceinline__ void run(const float*, const float*, int,
                                               float (&)[4], float (&)[4]) {}
};

// Stage A compute: warp = (parity P, j-group JG); thread = row lane.
template<int P, int JG>
__device__ __forceinline__ void stageA_compute(const float* sm, float* sT, int lane, int q)
{
    const float* fc = sm + (P ? F_CO : F_CE);
    const float* fs = sm + (P ? F_SO : F_SE);
    float accC[4] = {0.f, 0.f, 0.f, 0.f};
    float accS[4] = {0.f, 0.f, 0.f, 0.f};

    AChain<P, JG, 1>::run(fc, fs, lane, accC, accS);

    float x0 = sm[F_CE + lane], x128 = sm[F_CO + lane];
    float u64v = sm[F_SE + lane], v64v = sm[F_SO + lane];
#pragma unroll
    for (int jj = 0; jj < 4; jj++) {
        const int j = JG * 4 + jj;
        if (P == 0) {
            accC[jj] += x0 + x128 + ((j & 1) ? -u64v : u64v);
        } else {
            accC[jj] += x0 - x128;
            accS[jj] += (j & 1) ? -v64v : v64v;
        }
    }
    const int row = q * 32 + lane;
#pragma unroll
    for (int jj = 0; jj < 4; jj++) {
        const int k = 2 * (JG * 4 + jj) + P;
        sT[k * 256 + (row ^ (k & 31))]        = accC[jj];
        sT[(32 + k) * 256 + (row ^ (k & 31))] = accS[jj];
    }
}

// ---------------------------------------------------------------------------
// Stage B inner machinery: batched (4 n / group -> 16 independent LDS).
// ---------------------------------------------------------------------------
template<int P, int JH, int N, int JJ> struct BFma {
    static __device__ __forceinline__ void f(float cs, float ss,
                                             float (&aA)[8], float (&aB)[8]) {
        constexpr int   K  = 2 * (JH * 8 + JJ) + P;
        constexpr float cc = (float)k_cos256(N * K);
        aA[JJ] = fmaf(cs, cc, aA[JJ]);
        if constexpr (K > 0) {
            constexpr float sn = (float)k_cos256(N * K + 192);
            aB[JJ] = fmaf(ss, sn, aB[JJ]);
        }
    }
};

template<int P, int JH, int N0, int CNT, int T> struct BGg {
    static __device__ __forceinline__ void f(const float* cs, const float* ss,
                                             float (&aA)[8], float (&aB)[8]) {
        BFma<P, JH, N0 + T, 0>::f(cs[T], ss[T], aA, aB);
        BFma<P, JH, N0 + T, 1>::f(cs[T], ss[T], aA, aB);
        BFma<P, JH, N0 + T, 2>::f(cs[T], ss[T], aA, aB);
        BFma<P, JH, N0 + T, 3>::f(cs[T], ss[T], aA, aB);
        BFma<P, JH, N0 + T, 4>::f(cs[T], ss[T], aA, aB);
        BFma<P, JH, N0 + T, 5>::f(cs[T], ss[T], aA, aB);
        BFma<P, JH, N0 + T, 6>::f(cs[T], ss[T], aA, aB);
        BFma<P, JH, N0 + T, 7>::f(cs[T], ss[T], aA, aB);
        BGg<P, JH, N0, CNT, T + 1>::f(cs, ss, aA, aB);
    }
};
template<int P, int JH, int N0, int CNT> struct BGg<P, JH, N0, CNT, CNT> {
    static __device__ __forceinline__ void f(const float*, const float*,
                                             float (&)[8], float (&)[8]) {}
};

template<int P, int JH, int N0> struct BChain {
    static constexpr int CNT = (64 - N0) < 4 ? (64 - N0) : 4;
    static __device__ __forceinline__ void run(const float* col, int cb,
                                               float (&aA)[8], float (&aB)[8]) {
        float av[CNT], bv[CNT], ev[CNT], dv[CNT];
#pragma unroll
        for (int t = 0; t < CNT; t++) {
            av[t] = col[(N0 + t) ^ cb];
            bv[t] = col[(256 - (N0 + t)) ^ cb];
            ev[t] = col[(128 - (N0 + t)) ^ cb];
            dv[t] = col[(128 + (N0 + t)) ^ cb];
        }
        float cs[CNT], ss[CNT];
#pragma unroll
        for (int t = 0; t < CNT; t++) {
            if (P == 0) { cs[t] = (av[t] + bv[t]) + (ev[t] + dv[t]);
                          ss[t] = (av[t] - bv[t]) - (ev[t] - dv[t]); }
            else        { cs[t] = (av[t] + bv[t]) - (ev[t] + dv[t]);
                          ss[t] = (av[t] - bv[t]) + (ev[t] - dv[t]); }
        }
        BGg<P, JH, N0, CNT, 0>::f(cs, ss, aA, aB);
        BChain<P, JH, N0 + CNT>::run(col, cb, aA, aB);
    }
};
template<int P, int JH> struct BChain<P, JH, 64> {
    static __device__ __forceinline__ void run(const float*, int,
                                               float (&)[8], float (&)[8]) {}
};

template<int P, int JH>
__device__ __forceinline__ void stageB_compute(const float* sT, float* sm, int c)
{
    const int cb = c & 31;
    const float* col = sT + c * 256;
    float aA[8] = {0.f,0.f,0.f,0.f,0.f,0.f,0.f,0.f};
    float aB[8] = {0.f,0.f,0.f,0.f,0.f,0.f,0.f,0.f};

    BChain<P, JH, 1>::run(col, cb, aA, aB);

    float s0 = col[0 ^ cb], s64 = col[64 ^ cb];
    float s128 = col[128 ^ cb], s192 = col[192 ^ cb];
#pragma unroll
    for (int jj = 0; jj < 8; jj++) {
        const int j = JH * 8 + jj;
        const int k = 2 * j + P;
        if (P == 0) {
            float pe = s64 + s192;
            aA[jj] += s0 + s128 + ((j & 1) ? -pe : pe);
        } else {
            float po = s64 - s192;
            aA[jj] += s0 - s128;
            aB[jj] += (j & 1) ? -po : po;
        }
        sm[RA + c * 33 + k] = aA[jj];
        sm[RB + c * 33 + k] = aB[jj];
    }
}

// ---------------------------------------------------------------------------
// Fold phase: load (gmem -> regs) + store (fold arith -> smem), pipelined.
// ---------------------------------------------------------------------------
__device__ __forceinline__ void loadA(float (&v)[32], const float* src, int tid, int q)
{
    const float* rows = src + q * 32 * 256;
    const int n = tid & 63;
    const int rbase = tid >> 6;
#pragma unroll
    for (int it = 0; it < 8; it++) {
        const float* row = rows + (rbase + it * 4) * 256;
        if (n == 0) {
            v[it*4+0] = row[0];   v[it*4+1] = row[128];
            v[it*4+2] = row[64];  v[it*4+3] = row[192];
        } else {
            v[it*4+0] = row[n];        v[it*4+1] = row[256 - n];
            v[it*4+2] = row[128 - n];  v[it*4+3] = row[128 + n];
        }
    }
}

__device__ __forceinline__ void storeA(float* sm, const float (&v)[32], int tid)
{
    const int n = tid & 63;
    const int rbase = tid >> 6;
#pragma unroll
    for (int it = 0; it < 8; it++) {
        const int r = rbase + it * 4;
        float a = v[it*4+0], b = v[it*4+1], e = v[it*4+2], d = v[it*4+3];
        if (n == 0) {
            sm[F_CE + r] = a;
            sm[F_CO + r] = b;
            sm[F_SE + r] = e + d;
            sm[F_SO + r] = e - d;
        } else {
            sm[F_CE + n * 33 + r] = (a + b) + (e + d);
            sm[F_CO + n * 33 + r] = (a + b) - (e + d);
            sm[F_SE + n * 33 + r] = (a - b) - (e - d);
            sm[F_SO + n * 33 + r] = (a - b) + (e - d);
        }
    }
}

// ---------------------------------------------------------------------------
// K1: fused rfft2.  CTA = one image.  __launch_bounds__(256, 2): reg cap 128
// (smem pins occupancy at 2 CTAs anyway) -> room for LDS lookahead batches.
// ---------------------------------------------------------------------------
__global__ __launch_bounds__(256, 2) void k_rfft2(const float* __restrict__ pred,
                                                  const float* __restrict__ gt)
{
    extern __shared__ float sm[];
    float* sT = sm + OT;

    const int img = blockIdx.x;
    const float* src = (img < NIMG) ? pred + (size_t)img * 65536
                                    : gt   + (size_t)(img - NIMG) * 65536;
    const int tid  = threadIdx.x;
    const int wid  = tid >> 5;
    const int lane = tid & 31;

    float v[32];
    loadA(v, src, tid, 0);

#pragma unroll 1
    for (int q = 0; q < 8; q++) {
        storeA(sm, v, tid);
        __syncthreads();
        if (q < 7) loadA(v, src, tid, q + 1);   // overlap with compute below
        switch (wid) {
            case 0: stageA_compute<0, 0>(sm, sT, lane, q); break;
            case 1: stageA_compute<1, 0>(sm, sT, lane, q); break;
            case 2: stageA_compute<0, 1>(sm, sT, lane, q); break;
            case 3: stageA_compute<1, 1>(sm, sT, lane, q); break;
            case 4: stageA_compute<0, 2>(sm, sT, lane, q); break;
            case 5: stageA_compute<1, 2>(sm, sT, lane, q); break;
            case 6: stageA_compute<0, 3>(sm, sT, lane, q); break;
            case 7: stageA_compute<1, 3>(sm, sT, lane, q); break;
        }
        __syncthreads();
    }

    // Stage B: fold-on-the-fly column DFT of sT (results into fold area).
    {
        const int c = (wid >> 2) * 32 + lane;
        switch (wid & 3) {
            case 0: stageB_compute<0, 0>(sT, sm, c); break;
            case 1: stageB_compute<1, 0>(sT, sm, c); break;
            case 2: stageB_compute<0, 1>(sT, sm, c); break;
            case 3: stageB_compute<1, 1>(sT, sm, c); break;
        }
    }
    __syncthreads();

    // Combine partials into complex modes; coalesced writes.
    float* mp = g_modes + (size_t)img * 2048;
#pragma unroll
    for (int t = 0; t < 4; t++) {
        int idx = tid + t * 256;
        int k1 = idx >> 5, k2 = idx & 31;
        float ATc = sm[RA + k2 * 33 + k1];
        float ATs = sm[RA + (32 + k2) * 33 + k1];
        float BTc = sm[RB + k2 * 33 + k1];
        float BTs = sm[RB + (32 + k2) * 33 + k1];
        mp[idx]        = ATc - BTs;
        mp[1024 + idx] = -(BTc + ATs);
    }
}

// ---------------------------------------------------------------------------
// K2: fused MLP + epilogue with f32x2 packing (R13-passing, unchanged).
// ---------------------------------------------------------------------------
__global__ __launch_bounds__(256) void k_mlp_epi(const float* __restrict__ W1,
                                                 const float* __restrict__ b1,
                                                 const float* __restrict__ W2,
                                                 const float* __restrict__ b2,
                                                 const float* __restrict__ W3,
                                                 const float* __restrict__ b3,
                                                 float* __restrict__ out)
{
    __shared__ float sW1[128], sb1[64], sb2[32], sW3[32], sb3v;
    __shared__ __align__(16) float sW2[2048];
    __shared__ float sRed[256];
    __shared__ float sTe;
    const int tid = threadIdx.x;
    const int img = blockIdx.x;

    for (int i = tid; i < 128;  i += 256) sW1[i] = W1[i];
    for (int i = tid; i < 2048; i += 256) sW2[i] = W2[i];
    if (tid < 64) sb1[tid] = b1[tid];
    if (tid < 32) { sb2[tid] = b2[tid]; sW3[tid] = W3[tid]; }
    if (tid == 0) sb3v = b3[0];
    __syncthreads();

    const float* mp = g_modes + (size_t)img * 2048;
    const float* mg = g_modes + (size_t)(NIMG + img) * 2048;
    const int base = img * 1024;

    float ev[4], uv[4];
    float eSum = 0.f;

#pragma unroll 1
    for (int bi = 0; bi < 2; bi++) {
        const int i0 = tid + bi * 512;
        const int i1 = i0 + 256;
        float pr0 = mp[i0], pi0 = mp[1024 + i0];
        float pr1 = mp[i1], pi1 = mp[1024 + i1];
        float gr0 = mg[i0], gi0 = mg[1024 + i0];
        float gr1 = mg[i1], gi1 = mg[1024 + i1];

        float E0 = fmaf(pr0, pr0, pi0 * pi0);
        float E1 = fmaf(pr1, pr1, pi1 * pi1);
        out[OFF_E + base + i0] = E0;
        out[OFF_E + base + i1] = E1;
        float d0r = pr0 - gr0, d0i = pi0 - gi0;
        float d1r = pr1 - gr1, d1i = pi1 - gi1;
        out[OFF_ERR + base + i0] = fmaf(d0r, d0r, d0i * d0i);
        out[OFF_ERR + base + i1] = fmaf(d1r, d1r, d1i * d1i);
        ev[bi * 2] = E0; ev[bi * 2 + 1] = E1;
        eSum += E0 + E1;

        u64p h2a2[16], h2b2[16];
#pragma unroll
        for (int q = 0; q < 16; q++) {
            u64p b2p = pk2(sb2[2 * q], sb2[2 * q + 1]);
            h2a2[q] = b2p;
            h2b2[q] = b2p;
        }

#pragma unroll 8
        for (int i = 0; i < 64; i++) {
            float w1a = sW1[i], w1b = sW1[64 + i], bb = sb1[i];
            float a0 = fmaf(pr0, w1a, fmaf(pi0, w1b, bb));
            float a1 = fmaf(pr1, w1a, fmaf(pi1, w1b, bb));
            a0 = a0 > 0.f ? a0 : 0.f;
            a1 = a1 > 0.f ? a1 : 0.f;
            u64p a0p = dup2(a0);
            u64p a1p = dup2(a1);
            const ulonglong2* w2p = (const ulonglong2*)(sW2 + i * 32);
#pragma unroll
            for (int q = 0; q < 8; q++) {
                ulonglong2 wp = w2p[q];
                h2a2[2*q]   = fma2(a0p, wp.x, h2a2[2*q]);
                h2a2[2*q+1] = fma2(a0p, wp.y, h2a2[2*q+1]);
                h2b2[2*q]   = fma2(a1p, wp.x, h2b2[2*q]);
                h2b2[2*q+1] = fma2(a1p, wp.y, h2b2[2*q+1]);
            }
        }
        float o0 = sb3v, o1 = sb3v;
#pragma unroll
        for (int q = 0; q < 16; q++) {
            float xa, ya, xb, yb;
            unpk2(h2a2[q], xa, ya);
            unpk2(h2b2[q], xb, yb);
            float w3x = sW3[2 * q], w3y = sW3[2 * q + 1];
            o0 = fmaf(xa > 0.f ? xa : 0.f, w3x, o0);
            o0 = fmaf(ya > 0.f ? ya : 0.f, w3y, o0);
            o1 = fmaf(xb > 0.f ? xb : 0.f, w3x, o1);
            o1 = fmaf(yb > 0.f ? yb : 0.f, w3y, o1);
        }
        float u0 = fmaxf(o0, 0.f) + log1pf(expf(-fabsf(o0)));
        float u1 = fmaxf(o1, 0.f) + log1pf(expf(-fabsf(o1)));
        out[OFF_U + base + i0] = u0;
        out[OFF_U + base + i1] = u1;
        uv[bi * 2] = u0; uv[bi * 2 + 1] = u1;
    }

    sRed[tid] = eSum;
    __syncthreads();
    for (int w = 128; w > 0; w >>= 1) {
        if (tid < w) sRed[tid] += sRed[tid + w];
        __syncthreads();
    }
    if (tid == 0) sTe = sRed[0];
    __syncthreads();
    const float te = sTe + 1e-8f;

#pragma unroll
    for (int b = 0; b < 4; b++) {
        int idx = tid + b * 256;
        float F = ev[b] / te;
        out[OFF_F + base + idx] = F;
        out[OFF_W + base + idx] = F * uv[b];
    }
}

// ---------------------------------------------------------------------------
// K3: per-mode stats (unchanged, known-good).
// ---------------------------------------------------------------------------
__global__ __launch_bounds__(256) void k_stats(float* __restrict__ out)
{
    __shared__ double red[6][256];
    const int tid = threadIdx.x;
    const int kl  = tid & 7;
    const int sg  = tid >> 3;                 // 0..31
    const int k   = blockIdx.x * 8 + kl;

    double su = 0, se = 0, sen = 0, sue = 0, suu = 0, see = 0;
    for (int s = sg; s < NIMG; s += 32) {
        float u  = out[OFF_U   + (size_t)s * 1024 + k];
        float e  = out[OFF_ERR + (size_t)s * 1024 + k];
        float en = out[OFF_E   + (size_t)s * 1024 + k];
        su += u; se += e; sen += en;
        sue += (double)u * (double)e;
        suu += (double)u * (double)u;
        see += (double)e * (double)e;
    }
    red[0][tid] = su;  red[1][tid] = se;  red[2][tid] = sen;
    red[3][tid] = sue; red[4][tid] = suu; red[5][tid] = see;
    __syncthreads();

    for (int off = 16; off >= 1; off >>= 1) {
        if (sg < off) {
#pragma unroll
            for (int m = 0; m < 6; m++)
                red[m][tid] += red[m][tid + off * 8];
        }
        __syncthreads();
    }
    if (tid < 8) {
        double tsu = red[0][tid], tse = red[1][tid], tsen = red[2][tid];
        double tsue = red[3][tid], tsuu = red[4][tid], tsee = red[5][tid];
        out[OFF_US + k] = (float)(tsu  * (1.0 / 512.0));
        out[OFF_ES + k] = (float)(tsen * (1.0 / 512.0));
        double num  = tsue - tsu * tse * (1.0 / 512.0);
        double varu = tsuu - tsu * tsu * (1.0 / 512.0);
        double vare = tsee - tse * tse * (1.0 / 512.0);
        out[OFF_CAL + k] = (float)(num / (sqrt(varu * vare) + 1e-8));
    }
}

// ---------------------------------------------------------------------------
extern "C" void kernel_launch(void* const* d_in, const int* in_sizes, int n_in,
                              void* d_out, int out_size)
{
    const float* pred = (const float*)d_in[0];
    // d_in[1] = uncertainty: unused by the reference
    const float* gt   = (const float*)d_in[2];
    const float* W1   = (const float*)d_in[3];
    const float* b1   = (const float*)d_in[4];
    const float* W2   = (const float*)d_in[5];
    const float* b2   = (const float*)d_in[6];
    const float* W3   = (const float*)d_in[7];
    const float* b3   = (const float*)d_in[8];
    float* out = (float*)d_out;

    const int smem1 = K1_FLOATS * 4;   // 99328 B
    cudaFuncSetAttribute(k_rfft2, cudaFuncAttributeMaxDynamicSharedMemorySize, smem1);

    k_rfft2<<<1024, 256, smem1>>>(pred, gt);
    k_mlp_epi<<<512, 256>>>(W1, b1, W2, b2, W3, b3, out);
    k_stats<<<128, 256>>>(out);
}

// round 15
// speedup vs baseline: 1.7203x; 1.0387x over previous
#include <cuda_runtime.h>
#include <math.h>

// Problem constants
#define NIMG 512          // B*C
#define NALL 1024         // pred + gt images

// Output offsets (tuple order, flattened)
#define OFF_E    0
#define OFF_U    524288
#define OFF_F    1048576
#define OFF_W    1572864
#define OFF_US   2097152
#define OFF_ES   2098176
#define OFF_ERR  2099200
#define OFF_CAL  2623488

// ---------------------------------------------------------------------------
// Compile-time twiddles -> FFMA immediates (template-parameter constexpr).
// ---------------------------------------------------------------------------
__host__ __device__ constexpr double k_cpi_taylor(double x) {  // cos(x)
    double term = 1.0, sum = 1.0, x2 = x * x;
    for (int j = 1; j <= 14; j++) { term *= -x2 / double((2*j-1)*(2*j)); sum += term; }
    return sum;
}
__host__ __device__ constexpr double k_cos256(int m) {         // cos(2*pi*m/256)
    m &= 255;
    if (m > 128) m = 256 - m;
    constexpr double PI = 3.14159265358979323846;
    if (m <= 64) return  k_cpi_taylor(PI * (double)m / 128.0);
    return -k_cpi_taylor(PI * (double)(128 - m) / 128.0);
}

// Global scratch
__device__ float g_T2[(size_t)NALL * 64 * 256];  // [img][c 0..63][row]; c<32: Tc, else Ts
__device__ float g_modes[(size_t)NALL * 2048];   // per image: [re 0..1023 | im 0..1023]

// ---------------------------------------------------------------------------
// Packed fp32x2 helpers (base sm_100 ISA; SASS FFMA2).
// ---------------------------------------------------------------------------
typedef unsigned long long u64p;
static __device__ __forceinline__ u64p pk2(float x, float y) {
    u64p r; asm("mov.b64 %0, {%1, %2};" : "=l"(r) : "f"(x), "f"(y)); return r;
}
static __device__ __forceinline__ u64p dup2(float x) {
    u64p r; asm("mov.b64 %0, {%1, %1};" : "=l"(r) : "f"(x)); return r;
}
static __device__ __forceinline__ void unpk2(u64p p, float& x, float& y) {
    asm("mov.b64 {%0, %1}, %2;" : "=f"(x), "=f"(y) : "l"(p));
}
static __device__ __forceinline__ u64p fma2(u64p a, u64p b, u64p c) {
    u64p d; asm("fma.rn.f32x2 %0, %1, %2, %3;" : "=l"(d) : "l"(a), "l"(b), "l"(c));
    return d;
}

// ===========================================================================
// Stage A kernel: row DFT.  33KB smem, launch_bounds(256,6) -> 48 warps/SM.
// ===========================================================================
#define F_CE 0
#define F_CO 2112
#define F_SE 4224
#define F_SO 6336
#define A_FLOATS 8448            // 33792 B

template<int P, int JG, int N, int JJ> struct FmaJ {
    static __device__ __forceinline__ void f(float cu, float sv,
                                             float (&aC)[4], float (&aS)[4]) {
        constexpr int   K  = 2 * (JG * 4 + JJ) + P;
        constexpr float cc = (float)k_cos256(N * K);
        aC[JJ] = fmaf(cu, cc, aC[JJ]);
        if constexpr (K > 0) {
            constexpr float ss = (float)k_cos256(N * K + 192);   // sin
            aS[JJ] = fmaf(sv, ss, aS[JJ]);
        }
    }
};

template<int P, int JG, int N0, int CNT, int T> struct AGg {
    static __device__ __forceinline__ void f(const float* cu, const float* sv,
                                             float (&aC)[4], float (&aS)[4]) {
        FmaJ<P, JG, N0 + T, 0>::f(cu[T], sv[T], aC, aS);
        FmaJ<P, JG, N0 + T, 1>::f(cu[T], sv[T], aC, aS);
        FmaJ<P, JG, N0 + T, 2>::f(cu[T], sv[T], aC, aS);
        FmaJ<P, JG, N0 + T, 3>::f(cu[T], sv[T], aC, aS);
        AGg<P, JG, N0, CNT, T + 1>::f(cu, sv, aC, aS);
    }
};
template<int P, int JG, int N0, int CNT> struct AGg<P, JG, N0, CNT, CNT> {
    static __device__ __forceinline__ void f(const float*, const float*,
                                             float (&)[4], float (&)[4]) {}
};

template<int P, int JG, int N0> struct AChain {
    static constexpr int CNT = (64 - N0) < 4 ? (64 - N0) : 4;
    static __device__ __forceinline__ void run(const float* fc, const float* fs, int lane,
                                               float (&aC)[4], float (&aS)[4]) {
        float cu[CNT], sv[CNT];
#pragma unroll
        for (int t = 0; t < CNT; t++) {
            cu[t] = fc[(N0 + t) * 33 + lane];
            sv[t] = fs[(N0 + t) * 33 + lane];
        }
        AGg<P, JG, N0, CNT, 0>::f(cu, sv, aC, aS);
        AChain<P, JG, N0 + CNT>::run(fc, fs, lane, aC, aS);
    }
};
template<int P, int JG> struct AChain<P, JG, 64> {
    static __device__ __forceinline__ void run(const float*, const float*, int,
                                               float (&)[4], float (&)[4]) {}
};

template<int P, int JG>
__device__ __forceinline__ void stageA_compute(const float* sm, float* gdst, int lane, int q)
{
    const float* fc = sm + (P ? F_CO : F_CE);
    const float* fs = sm + (P ? F_SO : F_SE);
    float accC[4] = {0.f, 0.f, 0.f, 0.f};
    float accS[4] = {0.f, 0.f, 0.f, 0.f};

    AChain<P, JG, 1>::run(fc, fs, lane, accC, accS);

    float x0 = sm[F_CE + lane], x128 = sm[F_CO + lane];
    float u64v = sm[F_SE + lane], v64v = sm[F_SO + lane];
#pragma unroll
    for (int jj = 0; jj < 4; jj++) {
        const int j = JG * 4 + jj;
        if (P == 0) {
            accC[jj] += x0 + x128 + ((j & 1) ? -u64v : u64v);
        } else {
            accC[jj] += x0 - x128;
            accS[jj] += (j & 1) ? -v64v : v64v;
        }
    }
    const int row = q * 32 + lane;
#pragma unroll
    for (int jj = 0; jj < 4; jj++) {
        const int k = 2 * (JG * 4 + jj) + P;
        gdst[k * 256 + row]        = accC[jj];   // coalesced: lanes = rows
        gdst[(32 + k) * 256 + row] = accS[jj];
    }
}

__global__ __launch_bounds__(256, 6) void k_stA(const float* __restrict__ pred,
                                                const float* __restrict__ gt)
{
    extern __shared__ float sm[];
    const int img = blockIdx.x;
    const float* src = (img < NIMG) ? pred + (size_t)img * 65536
                                    : gt   + (size_t)(img - NIMG) * 65536;
    float* gdst = g_T2 + (size_t)img * 16384;
    const int tid  = threadIdx.x;
    const int wid  = tid >> 5;
    const int lane = tid & 31;
    const int n    = tid & 63;
    const int rbase = tid >> 6;

#pragma unroll 1
    for (int q = 0; q < 8; q++) {
        if (q) __syncthreads();          // prior compute done -> fold buffers free
        const float* rows = src + q * 32 * 256;
#pragma unroll
        for (int it = 0; it < 8; it++) {
            const int r = rbase + it * 4;
            const float* row = rows + r * 256;
            if (n == 0) {
                sm[F_CE + r] = row[0];
                sm[F_CO + r] = row[128];
                float a = row[64], b = row[192];
                sm[F_SE + r] = a + b;
                sm[F_SO + r] = a - b;
            } else {
                float a = row[n], b = row[256 - n], e = row[128 - n], d = row[128 + n];
                sm[F_CE + n * 33 + r] = (a + b) + (e + d);
                sm[F_CO + n * 33 + r] = (a + b) - (e + d);
                sm[F_SE + n * 33 + r] = (a - b) - (e - d);
                sm[F_SO + n * 33 + r] = (a - b) + (e - d);
            }
        }
        __syncthreads();
        switch (wid) {
            case 0: stageA_compute<0, 0>(sm, gdst, lane, q); break;
            case 1: stageA_compute<1, 0>(sm, gdst, lane, q); break;
            case 2: stageA_compute<0, 1>(sm, gdst, lane, q); break;
            case 3: stageA_compute<1, 1>(sm, gdst, lane, q); break;
            case 4: stageA_compute<0, 2>(sm, gdst, lane, q); break;
            case 5: stageA_compute<1, 2>(sm, gdst, lane, q); break;
            case 6: stageA_compute<0, 3>(sm, gdst, lane, q); break;
            case 7: stageA_compute<1, 3>(sm, gdst, lane, q); break;
        }
    }
}

// ===========================================================================
// Stage B kernel: column DFT.  512 threads, 66.5KB smem, (512,3) -> 48 warps.
// Fold-on-load into stride-65 arrays; warp = (c-half, P, JH).
// ===========================================================================
#define B_PE 0
#define B_PO 4095
#define B_QE 8190
#define B_QO 12285
#define B_SP 16380               // [4][64] specials: col 0,64,128,192
#define B_FLOATS 16636           // 66544 B
#define B_RA 0                   // results reuse fold area after sync
#define B_RB 2112

template<int P, int JH, int N, int JJ> struct BFma {
    static __device__ __forceinline__ void f(float cs, float ss,
                                             float (&aA)[4], float (&aB)[4]) {
        constexpr int   K  = 2 * (JH * 4 + JJ) + P;
        constexpr float cc = (float)k_cos256(N * K);
        aA[JJ] = fmaf(cs, cc, aA[JJ]);
        if constexpr (K > 0) {
            constexpr float sn = (float)k_cos256(N * K + 192);
            aB[JJ] = fmaf(ss, sn, aB[JJ]);
        }
    }
};

template<int P, int JH, int N0, int CNT, int T> struct BGg {
    static __device__ __forceinline__ void f(const float* cs, const float* ss,
                                             float (&aA)[4], float (&aB)[4]) {
        BFma<P, JH, N0 + T, 0>::f(cs[T], ss[T], aA, aB);
        BFma<P, JH, N0 + T, 1>::f(cs[T], ss[T], aA, aB);
        BFma<P, JH, N0 + T, 2>::f(cs[T], ss[T], aA, aB);
        BFma<P, JH, N0 + T, 3>::f(cs[T], ss[T], aA, aB);
        BGg<P, JH, N0, CNT, T + 1>::f(cs, ss, aA, aB);
    }
};
template<int P, int JH, int N0, int CNT> struct BGg<P, JH, N0, CNT, CNT> {
    static __device__ __forceinline__ void f(const float*, const float*,
                                             float (&)[4], float (&)[4]) {}
};

template<int P, int JH, int N0> struct BChain {
    static constexpr int CNT = (64 - N0) < 4 ? (64 - N0) : 4;
    static __device__ __forceinline__ void run(const float* pc, const float* qc, int c,
                                               float (&aA)[4], float (&aB)[4]) {
        float cs[CNT], ss[CNT];
#pragma unroll
        for (int t = 0; t < CNT; t++) {
            cs[t] = pc[(N0 + t - 1) * 65 + c];
            ss[t] = qc[(N0 + t - 1) * 65 + c];
        }
        BGg<P, JH, N0, CNT, 0>::f(cs, ss, aA, aB);
        BChain<P, JH, N0 + CNT>::run(pc, qc, c, aA, aB);
    }
};
template<int P, int JH> struct BChain<P, JH, 64> {
    static __device__ __forceinline__ void run(const float*, const float*, int,
                                               float (&)[4], float (&)[4]) {}
};

template<int P, int JH>
__device__ __forceinline__ void stB_compute(const float* sm, int c,
                                            float (&aA)[4], float (&aB)[4])
{
    const float* pc = sm + (P ? B_PO : B_PE);
    const float* qc = sm + (P ? B_QO : B_QE);
#pragma unroll
    for (int jj = 0; jj < 4; jj++) { aA[jj] = 0.f; aB[jj] = 0.f; }

    BChain<P, JH, 1>::run(pc, qc, c, aA, aB);

    float s0   = sm[B_SP + c];
    float s64  = sm[B_SP + 64 + c];
    float s128 = sm[B_SP + 128 + c];
    float s192 = sm[B_SP + 192 + c];
#pragma unroll
    for (int jj = 0; jj < 4; jj++) {
        const int j = JH * 4 + jj;
        if (P == 0) {
            float pe = s64 + s192;
            aA[jj] += s0 + s128 + ((j & 1) ? -pe : pe);
        } else {
            float po = s64 - s192;
            aA[jj] += s0 - s128;
            aB[jj] += (j & 1) ? -po : po;
        }
    }
}

__global__ __launch_bounds__(512, 3) void k_stB()
{
    extern __shared__ float sm[];
    const int img = blockIdx.x;
    const int tid = threadIdx.x;
    const int wid = tid >> 5, lane = tid & 31;
    const float* base = g_T2 + (size_t)img * 16384;

    // Fold-on-load: lanes sweep n within a column (coalesced LDG);
    // stride-65 STS conflict-free.
    {
        const int n  = tid & 63;
        const int cg = tid >> 6;             // 0..7
#pragma unroll 1
        for (int itc = 0; itc < 8; itc++) {
            const int c = cg + itc * 8;
            const float* col = base + c * 256;
            if (n == 0) {
                sm[B_SP + c]       = col[0];
                sm[B_SP + 64 + c]  = col[64];
                sm[B_SP + 128 + c] = col[128];
                sm[B_SP + 192 + c] = col[192];
            } else {
                float a = col[n], b = col[256 - n], e = col[128 - n], d = col[128 + n];
                sm[B_PE + (n - 1) * 65 + c] = (a + b) + (e + d);
                sm[B_PO + (n - 1) * 65 + c] = (a + b) - (e + d);
                sm[B_QE + (n - 1) * 65 + c] = (a - b) - (e - d);
                sm[B_QO + (n - 1) * 65 + c] = (a - b) + (e - d);
            }
        }
    }
    __syncthreads();

    // Compute: 16 warps = (c-half, P, JH); 4 k per thread.
    const int c   = lane + (wid >> 3) * 32;
    const int sub = wid & 7;                 // P = sub&1, JH = sub>>1
    float aA[4], aB[4];
    switch (sub) {
        case 0: stB_compute<0, 0>(sm, c, aA, aB); break;
        case 1: stB_compute<1, 0>(sm, c, aA, aB); break;
        case 2: stB_compute<0, 1>(sm, c, aA, aB); break;
        case 3: stB_compute<1, 1>(sm, c, aA, aB); break;
        case 4: stB_compute<0, 2>(sm, c, aA, aB); break;
        case 5: stB_compute<1, 2>(sm, c, aA, aB); break;
        case 6: stB_compute<0, 3>(sm, c, aA, aB); break;
        case 7: stB_compute<1, 3>(sm, c, aA, aB); break;
    }
    __syncthreads();                         // fold-array reads complete

    {
        const int P = sub & 1, JH = sub >> 1;
#pragma unroll
        for (int jj = 0; jj < 4; jj++) {
            const int k = 2 * (JH * 4 + jj) + P;
            sm[B_RA + c * 33 + k] = aA[jj];
            sm[B_RB + c * 33 + k] = aB[jj];
        }
    }
    __syncthreads();

    // Combine into complex modes; coalesced writes.
    float* mp = g_modes + (size_t)img * 2048;
#pragma unroll
    for (int t = 0; t < 2; t++) {
        int idx = tid + t * 512;
        int k1 = idx >> 5, k2 = idx & 31;
        float ATc = sm[B_RA + k2 * 33 + k1];
        float ATs = sm[B_RA + (32 + k2) * 33 + k1];
        float BTc = sm[B_RB + k2 * 33 + k1];
        float BTs = sm[B_RB + (32 + k2) * 33 + k1];
        mp[idx]        = ATc - BTs;
        mp[1024 + idx] = -(BTc + ATs);
    }
}

// ===========================================================================
// K2: fused MLP + epilogue with f32x2 packing (R13/R14-passing, unchanged).
// ===========================================================================
__global__ __launch_bounds__(256) void k_mlp_epi(const float* __restrict__ W1,
                                                 const float* __restrict__ b1,
                                                 const float* __restrict__ W2,
                                                 const float* __restrict__ b2,
                                                 const float* __restrict__ W3,
                                                 const float* __restrict__ b3,
                                                 float* __restrict__ out)
{
    __shared__ float sW1[128], sb1[64], sb2[32], sW3[32], sb3v;
    __shared__ __align__(16) float sW2[2048];
    __shared__ float sRed[256];
    __shared__ float sTe;
    const int tid = threadIdx.x;
    const int img = blockIdx.x;

    for (int i = tid; i < 128;  i += 256) sW1[i] = W1[i];
    for (int i = tid; i < 2048; i += 256) sW2[i] = W2[i];
    if (tid < 64) sb1[tid] = b1[tid];
    if (tid < 32) { sb2[tid] = b2[tid]; sW3[tid] = W3[tid]; }
    if (tid == 0) sb3v = b3[0];
    __syncthreads();

    const float* mp = g_modes + (size_t)img * 2048;
    const float* mg = g_modes + (size_t)(NIMG + img) * 2048;
    const int base = img * 1024;

    float ev[4], uv[4];
    float eSum = 0.f;

#pragma unroll 1
    for (int bi = 0; bi < 2; bi++) {
        const int i0 = tid + bi * 512;
        const int i1 = i0 + 256;
        float pr0 = mp[i0], pi0 = mp[1024 + i0];
        float pr1 = mp[i1], pi1 = mp[1024 + i1];
        float gr0 = mg[i0], gi0 = mg[1024 + i0];
        float gr1 = mg[i1], gi1 = mg[1024 + i1];

        float E0 = fmaf(pr0, pr0, pi0 * pi0);
        float E1 = fmaf(pr1, pr1, pi1 * pi1);
        out[OFF_E + base + i0] = E0;
        out[OFF_E + base + i1] = E1;
        float d0r = pr0 - gr0, d0i = pi0 - gi0;
        float d1r = pr1 - gr1, d1i = pi1 - gi1;
        out[OFF_ERR + base + i0] = fmaf(d0r, d0r, d0i * d0i);
        out[OFF_ERR + base + i1] = fmaf(d1r, d1r, d1i * d1i);
        ev[bi * 2] = E0; ev[bi * 2 + 1] = E1;
        eSum += E0 + E1;

        u64p h2a2[16], h2b2[16];
#pragma unroll
        for (int q = 0; q < 16; q++) {
            u64p b2p = pk2(sb2[2 * q], sb2[2 * q + 1]);
            h2a2[q] = b2p;
            h2b2[q] = b2p;
        }

#pragma unroll 8
        for (int i = 0; i < 64; i++) {
            float w1a = sW1[i], w1b = sW1[64 + i], bb = sb1[i];
            float a0 = fmaf(pr0, w1a, fmaf(pi0, w1b, bb));
            float a1 = fmaf(pr1, w1a, fmaf(pi1, w1b, bb));
            a0 = a0 > 0.f ? a0 : 0.f;
            a1 = a1 > 0.f ? a1 : 0.f;
            u64p a0p = dup2(a0);
            u64p a1p = dup2(a1);
            const ulonglong2* w2p = (const ulonglong2*)(sW2 + i * 32);
#pragma unroll
            for (int q = 0; q < 8; q++) {
                ulonglong2 wp = w2p[q];
                h2a2[2*q]   = fma2(a0p, wp.x, h2a2[2*q]);
                h2a2[2*q+1] = fma2(a0p, wp.y, h2a2[2*q+1]);
                h2b2[2*q]   = fma2(a1p, wp.x, h2b2[2*q]);
                h2b2[2*q+1] = fma2(a1p, wp.y, h2b2[2*q+1]);
            }
        }
        float o0 = sb3v, o1 = sb3v;
#pragma unroll
        for (int q = 0; q < 16; q++) {
            float xa, ya, xb, yb;
            unpk2(h2a2[q], xa, ya);
            unpk2(h2b2[q], xb, yb);
            float w3x = sW3[2 * q], w3y = sW3[2 * q + 1];
            o0 = fmaf(xa > 0.f ? xa : 0.f, w3x, o0);
            o0 = fmaf(ya > 0.f ? ya : 0.f, w3y, o0);
            o1 = fmaf(xb > 0.f ? xb : 0.f, w3x, o1);
            o1 = fmaf(yb > 0.f ? yb : 0.f, w3y, o1);
        }
        float u0 = fmaxf(o0, 0.f) + log1pf(expf(-fabsf(o0)));
        float u1 = fmaxf(o1, 0.f) + log1pf(expf(-fabsf(o1)));
        out[OFF_U + base + i0] = u0;
        out[OFF_U + base + i1] = u1;
        uv[bi * 2] = u0; uv[bi * 2 + 1] = u1;
    }

    sRed[tid] = eSum;
    __syncthreads();
    for (int w = 128; w > 0; w >>= 1) {
        if (tid < w) sRed[tid] += sRed[tid + w];
        __syncthreads();
    }
    if (tid == 0) sTe = sRed[0];
    __syncthreads();
    const float te = sTe + 1e-8f;

#pragma unroll
    for (int b = 0; b < 4; b++) {
        int idx = tid + b * 256;
        float F = ev[b] / te;
        out[OFF_F + base + idx] = F;
        out[OFF_W + base + idx] = F * uv[b];
    }
}

// ===========================================================================
// K3: per-mode stats (unchanged, known-good).
// ===========================================================================
__global__ __launch_bounds__(256) void k_stats(float* __restrict__ out)
{
    __shared__ double red[6][256];
    const int tid = threadIdx.x;
    const int kl  = tid & 7;
    const int sg  = tid >> 3;                 // 0..31
    const int k   = blockIdx.x * 8 + kl;

    double su = 0, se = 0, sen = 0, sue = 0, suu = 0, see = 0;
    for (int s = sg; s < NIMG; s += 32) {
        float u  = out[OFF_U   + (size_t)s * 1024 + k];
        float e  = out[OFF_ERR + (size_t)s * 1024 + k];
        float en = out[OFF_E   + (size_t)s * 1024 + k];
        su += u; se += e; sen += en;
        sue += (double)u * (double)e;
        suu += (double)u * (double)u;
        see += (double)e * (double)e;
    }
    red[0][tid] = su;  red[1][tid] = se;  red[2][tid] = sen;
    red[3][tid] = sue; red[4][tid] = suu; red[5][tid] = see;
    __syncthreads();

    for (int off = 16; off >= 1; off >>= 1) {
        if (sg < off) {
#pragma unroll
            for (int m = 0; m < 6; m++)
                red[m][tid] += red[m][tid + off * 8];
        }
        __syncthreads();
    }
    if (tid < 8) {
        double tsu = red[0][tid], tse = red[1][tid], tsen = red[2][tid];
        double tsue = red[3][tid], tsuu = red[4][tid], tsee = red[5][tid];
        out[OFF_US + k] = (float)(tsu  * (1.0 / 512.0));
        out[OFF_ES + k] = (float)(tsen * (1.0 / 512.0));
        double num  = tsue - tsu * tse * (1.0 / 512.0);
        double varu = tsuu - tsu * tsu * (1.0 / 512.0);
        double vare = tsee - tse * tse * (1.0 / 512.0);
        out[OFF_CAL + k] = (float)(num / (sqrt(varu * vare) + 1e-8));
    }
}

// ---------------------------------------------------------------------------
extern "C" void kernel_launch(void* const* d_in, const int* in_sizes, int n_in,
                              void* d_out, int out_size)
{
    const float* pred = (const float*)d_in[0];
    // d_in[1] = uncertainty: unused by the reference
    const float* gt   = (const float*)d_in[2];
    const float* W1   = (const float*)d_in[3];
    const float* b1   = (const float*)d_in[4];
    const float* W2   = (const float*)d_in[5];
    const float* b2   = (const float*)d_in[6];
    const float* W3   = (const float*)d_in[7];
    const float* b3   = (const float*)d_in[8];
    float* out = (float*)d_out;

    const int smemA = A_FLOATS * 4;   // 33792 B (< 48KB, no attribute needed)
    const int smemB = B_FLOATS * 4;   // 66544 B
    cudaFuncSetAttribute(k_stB, cudaFuncAttributeMaxDynamicSharedMemorySize, smemB);

    k_stA<<<1024, 256, smemA>>>(pred, gt);
    k_stB<<<1024, 512, smemB>>>();
    k_mlp_epi<<<512, 256>>>(W1, b1, W2, b2, W3, b3, out);
    k_stats<<<128, 256>>>(out);
}

// round 16
// speedup vs baseline: 2.0045x; 1.1652x over previous
#include <cuda_runtime.h>
#include <math.h>

// Problem constants
#define NIMG 512          // B*C
#define NALL 1024         // pred + gt images

// Output offsets (tuple order, flattened)
#define OFF_E    0
#define OFF_U    524288
#define OFF_F    1048576
#define OFF_W    1572864
#define OFF_US   2097152
#define OFF_ES   2098176
#define OFF_ERR  2099200
#define OFF_CAL  2623488

// Global scratch
__device__ float g_T2[(size_t)NALL * 64 * 256];  // [img][c 0..63][row]; c<32: Tc, else Ts
__device__ float g_modes[(size_t)NALL * 2048];   // per image: [re 0..1023 | im 0..1023]

// ---------------------------------------------------------------------------
// Packed fp32x2 helpers (base sm_100 ISA; SASS FFMA2).
// ---------------------------------------------------------------------------
typedef unsigned long long u64p;
static __device__ __forceinline__ u64p pk2(float x, float y) {
    u64p r; asm("mov.b64 %0, {%1, %2};" : "=l"(r) : "f"(x), "f"(y)); return r;
}
static __device__ __forceinline__ u64p dup2(float x) {
    u64p r; asm("mov.b64 %0, {%1, %1};" : "=l"(r) : "f"(x)); return r;
}
static __device__ __forceinline__ void unpk2(u64p p, float& x, float& y) {
    asm("mov.b64 {%0, %1}, %2;" : "=f"(x), "=f"(y) : "l"(p));
}
static __device__ __forceinline__ u64p fma2(u64p a, u64p b, u64p c) {
    u64p d; asm("fma.rn.f32x2 %0, %1, %2, %3;" : "=l"(d) : "l"(a), "l"(b), "l"(c));
    return d;
}

// ===========================================================================
// Stage A kernel: row DFT.  One small shared loop body for ALL warps;
// twiddles in per-CTA smem tables [parity][n][j] -> broadcast LDS.128.
// smem = 50176 B -> 4 CTAs/SM (32 warps).
// ===========================================================================
#define F_CE 0
#define F_CO 2112
#define F_SE 4224
#define F_SO 6336
#define TWA_C 8448
#define TWA_S 10496
#define A_FLOATS 12544           // 50176 B

static __device__ __forceinline__ void gen_tables(float* sm, int twc, int tws,
                                                  int tid, int nthr)
{
    for (int i = tid; i < 2048; i += nthr) {
        int p = i >> 10, rem = i & 1023, n = rem >> 4, j = rem & 15;
        int m = (n * (2 * j + p)) & 255;
        float x = (float)m * (1.0f / 128.0f);
        sm[twc + i] = cospif(x);
        sm[tws + i] = sinpif(x);
    }
}

static __device__ __forceinline__ void stA_comp(const float* sm, float* gdst,
                                                int lane, int q, int P, int JG)
{
    const float* fc = sm + (P ? F_CO : F_CE);
    const float* fs = sm + (P ? F_SO : F_SE);
    const float* tc = sm + TWA_C + P * 1024 + JG * 4;
    const float* ts = sm + TWA_S + P * 1024 + JG * 4;
    float aC[4] = {0.f, 0.f, 0.f, 0.f};
    float aS[4] = {0.f, 0.f, 0.f, 0.f};

#pragma unroll 7
    for (int n = 1; n < 64; n++) {
        float cu = fc[n * 33 + lane];
        float sv = fs[n * 33 + lane];
        float4 c4 = *(const float4*)(tc + n * 16);
        float4 s4 = *(const float4*)(ts + n * 16);
        aC[0] = fmaf(cu, c4.x, aC[0]);
        aC[1] = fmaf(cu, c4.y, aC[1]);
        aC[2] = fmaf(cu, c4.z, aC[2]);
        aC[3] = fmaf(cu, c4.w, aC[3]);
        aS[0] = fmaf(sv, s4.x, aS[0]);
        aS[1] = fmaf(sv, s4.y, aS[1]);
        aS[2] = fmaf(sv, s4.z, aS[2]);
        aS[3] = fmaf(sv, s4.w, aS[3]);
    }
    float x0 = sm[F_CE + lane], x128 = sm[F_CO + lane];
    float u64v = sm[F_SE + lane], v64v = sm[F_SO + lane];
    const int row = q * 32 + lane;
#pragma unroll
    for (int jj = 0; jj < 4; jj++) {
        int j = JG * 4 + jj;
        float sgn = (j & 1) ? -1.f : 1.f;
        float c = aC[jj], s = aS[jj];
        if (P == 0) {
            c += x0 + x128 + sgn * u64v;
        } else {
            c += x0 - x128;
            s += sgn * v64v;
        }
        int k = 2 * j + P;
        gdst[k * 256 + row]        = c;     // coalesced: lanes = rows
        gdst[(32 + k) * 256 + row] = s;
    }
}

__global__ __launch_bounds__(256, 4) void k_stA(const float* __restrict__ pred,
                                                const float* __restrict__ gt)
{
    extern __shared__ float sm[];
    const int img = blockIdx.x;
    const float* src = (img < NIMG) ? pred + (size_t)img * 65536
                                    : gt   + (size_t)(img - NIMG) * 65536;
    float* gdst = g_T2 + (size_t)img * 16384;
    const int tid   = threadIdx.x;
    const int wid   = tid >> 5;
    const int lane  = tid & 31;
    const int n     = tid & 63;
    const int rbase = tid >> 6;
    const int P     = wid & 1;
    const int JG    = wid >> 1;

    gen_tables(sm, TWA_C, TWA_S, tid, 256);

#pragma unroll 1
    for (int q = 0; q < 8; q++) {
        if (q) __syncthreads();          // prior compute done -> fold buffers free
        const float* rows = src + q * 32 * 256;
#pragma unroll
        for (int it = 0; it < 8; it++) {
            const int r = rbase + it * 4;
            const float* row = rows + r * 256;
            if (n == 0) {
                sm[F_CE + r] = row[0];
                sm[F_CO + r] = row[128];
                float a = row[64], b = row[192];
                sm[F_SE + r] = a + b;
                sm[F_SO + r] = a - b;
            } else {
                float a = row[n], b = row[256 - n], e = row[128 - n], d = row[128 + n];
                sm[F_CE + n * 33 + r] = (a + b) + (e + d);
                sm[F_CO + n * 33 + r] = (a + b) - (e + d);
                sm[F_SE + n * 33 + r] = (a - b) - (e - d);
                sm[F_SO + n * 33 + r] = (a - b) + (e - d);
            }
        }
        __syncthreads();                 // fold + (q==0) tables visible
        stA_comp(sm, gdst, lane, q, P, JG);
    }
}

// ===========================================================================
// Stage B kernel: column DFT.  512 threads, shared small body, smem tables.
// smem = 82928 B -> 2 CTAs/SM (32 warps).
// ===========================================================================
#define B_PE 0
#define B_PO 4095
#define B_QE 8190
#define B_QO 12285
#define B_SP 16380               // [4][64] specials: col 0,64,128,192
#define TWB_C 16636
#define TWB_S 18684
#define B_FLOATS 20732           // 82928 B
#define B_RA 0                   // results reuse fold area after sync
#define B_RB 2112

static __device__ __forceinline__ void stB_comp(const float* sm, int c, int P, int JH,
                                                float (&aA)[4], float (&aB)[4])
{
    const float* pc = sm + (P ? B_PO : B_PE);
    const float* qc = sm + (P ? B_QO : B_QE);
    const float* tc = sm + TWB_C + P * 1024 + JH * 4;
    const float* ts = sm + TWB_S + P * 1024 + JH * 4;
#pragma unroll
    for (int jj = 0; jj < 4; jj++) { aA[jj] = 0.f; aB[jj] = 0.f; }

#pragma unroll 7
    for (int nn = 1; nn < 64; nn++) {
        float cs = pc[(nn - 1) * 65 + c];
        float ss = qc[(nn - 1) * 65 + c];
        float4 c4 = *(const float4*)(tc + nn * 16);
        float4 s4 = *(const float4*)(ts + nn * 16);
        aA[0] = fmaf(cs, c4.x, aA[0]);
        aA[1] = fmaf(cs, c4.y, aA[1]);
        aA[2] = fmaf(cs, c4.z, aA[2]);
        aA[3] = fmaf(cs, c4.w, aA[3]);
        aB[0] = fmaf(ss, s4.x, aB[0]);
        aB[1] = fmaf(ss, s4.y, aB[1]);
        aB[2] = fmaf(ss, s4.z, aB[2]);
        aB[3] = fmaf(ss, s4.w, aB[3]);
    }
    float s0   = sm[B_SP + c];
    float s64  = sm[B_SP + 64 + c];
    float s128 = sm[B_SP + 128 + c];
    float s192 = sm[B_SP + 192 + c];
#pragma unroll
    for (int jj = 0; jj < 4; jj++) {
        int j = JH * 4 + jj;
        float sgn = (j & 1) ? -1.f : 1.f;
        if (P == 0) {
            aA[jj] += s0 + s128 + sgn * (s64 + s192);
        } else {
            aA[jj] += s0 - s128;
            aB[jj] += sgn * (s64 - s192);
        }
    }
}

__global__ __launch_bounds__(512, 2) void k_stB()
{
    extern __shared__ float sm[];
    const int img = blockIdx.x;
    const int tid = threadIdx.x;
    const int wid = tid >> 5, lane = tid & 31;
    const float* base = g_T2 + (size_t)img * 16384;

    gen_tables(sm, TWB_C, TWB_S, tid, 512);

    // Fold-on-load: lanes sweep n within a column (coalesced LDG);
    // stride-65 STS conflict-free.
    {
        const int n  = tid & 63;
        const int cg = tid >> 6;             // 0..7
#pragma unroll 1
        for (int itc = 0; itc < 8; itc++) {
            const int c = cg + itc * 8;
            const float* col = base + c * 256;
            if (n == 0) {
                sm[B_SP + c]       = col[0];
                sm[B_SP + 64 + c]  = col[64];
                sm[B_SP + 128 + c] = col[128];
                sm[B_SP + 192 + c] = col[192];
            } else {
                float a = col[n], b = col[256 - n], e = col[128 - n], d = col[128 + n];
                sm[B_PE + (n - 1) * 65 + c] = (a + b) + (e + d);
                sm[B_PO + (n - 1) * 65 + c] = (a + b) - (e + d);
                sm[B_QE + (n - 1) * 65 + c] = (a - b) - (e - d);
                sm[B_QO + (n - 1) * 65 + c] = (a - b) + (e - d);
            }
        }
    }
    __syncthreads();

    // Compute: 16 warps = (c-half, P, JH); 4 k per thread.
    const int c   = lane + (wid >> 3) * 32;
    const int sub = wid & 7;
    const int P   = sub & 1;
    const int JH  = sub >> 1;
    float aA[4], aB[4];
    stB_comp(sm, c, P, JH, aA, aB);
    __syncthreads();                         // fold-array reads complete

#pragma unroll
    for (int jj = 0; jj < 4; jj++) {
        const int k = 2 * (JH * 4 + jj) + P;
        sm[B_RA + c * 33 + k] = aA[jj];
        sm[B_RB + c * 33 + k] = aB[jj];
    }
    __syncthreads();

    // Combine into complex modes; coalesced writes.
    float* mp = g_modes + (size_t)img * 2048;
#pragma unroll
    for (int t = 0; t < 2; t++) {
        int idx = tid + t * 512;
        int k1 = idx >> 5, k2 = idx & 31;
        float ATc = sm[B_RA + k2 * 33 + k1];
        float ATs = sm[B_RA + (32 + k2) * 33 + k1];
        float BTc = sm[B_RB + k2 * 33 + k1];
        float BTs = sm[B_RB + (32 + k2) * 33 + k1];
        mp[idx]        = ATc - BTs;
        mp[1024 + idx] = -(BTc + ATs);
    }
}

// ===========================================================================
// K2: fused MLP + epilogue with f32x2 packing (R13/R15-passing, unchanged).
// ===========================================================================
__global__ __launch_bounds__(256) void k_mlp_epi(const float* __restrict__ W1,
                                                 const float* __restrict__ b1,
                                                 const float* __restrict__ W2,
                                                 const float* __restrict__ b2,
                                                 const float* __restrict__ W3,
                                                 const float* __restrict__ b3,
                                                 float* __restrict__ out)
{
    __shared__ float sW1[128], sb1[64], sb2[32], sW3[32], sb3v;
    __shared__ __align__(16) float sW2[2048];
    __shared__ float sRed[256];
    __shared__ float sTe;
    const int tid = threadIdx.x;
    const int img = blockIdx.x;

    for (int i = tid; i < 128;  i += 256) sW1[i] = W1[i];
    for (int i = tid; i < 2048; i += 256) sW2[i] = W2[i];
    if (tid < 64) sb1[tid] = b1[tid];
    if (tid < 32) { sb2[tid] = b2[tid]; sW3[tid] = W3[tid]; }
    if (tid == 0) sb3v = b3[0];
    __syncthreads();

    const float* mp = g_modes + (size_t)img * 2048;
    const float* mg = g_modes + (size_t)(NIMG + img) * 2048;
    const int base = img * 1024;

    float ev[4], uv[4];
    float eSum = 0.f;

#pragma unroll 1
    for (int bi = 0; bi < 2; bi++) {
        const int i0 = tid + bi * 512;
        const int i1 = i0 + 256;
        float pr0 = mp[i0], pi0 = mp[1024 + i0];
        float pr1 = mp[i1], pi1 = mp[1024 + i1];
        float gr0 = mg[i0], gi0 = mg[1024 + i0];
        float gr1 = mg[i1], gi1 = mg[1024 + i1];

        float E0 = fmaf(pr0, pr0, pi0 * pi0);
        float E1 = fmaf(pr1, pr1, pi1 * pi1);
        out[OFF_E + base + i0] = E0;
        out[OFF_E + base + i1] = E1;
        float d0r = pr0 - gr0, d0i = pi0 - gi0;
        float d1r = pr1 - gr1, d1i = pi1 - gi1;
        out[OFF_ERR + base + i0] = fmaf(d0r, d0r, d0i * d0i);
        out[OFF_ERR + base + i1] = fmaf(d1r, d1r, d1i * d1i);
        ev[bi * 2] = E0; ev[bi * 2 + 1] = E1;
        eSum += E0 + E1;

        u64p h2a2[16], h2b2[16];
#pragma unroll
        for (int q = 0; q < 16; q++) {
            u64p b2p = pk2(sb2[2 * q], sb2[2 * q + 1]);
            h2a2[q] = b2p;
            h2b2[q] = b2p;
        }

#pragma unroll 8
        for (int i = 0; i < 64; i++) {
            float w1a = sW1[i], w1b = sW1[64 + i], bb = sb1[i];
            float a0 = fmaf(pr0, w1a, fmaf(pi0, w1b, bb));
            float a1 = fmaf(pr1, w1a, fmaf(pi1, w1b, bb));
            a0 = a0 > 0.f ? a0 : 0.f;
            a1 = a1 > 0.f ? a1 : 0.f;
            u64p a0p = dup2(a0);
            u64p a1p = dup2(a1);
            const ulonglong2* w2p = (const ulonglong2*)(sW2 + i * 32);
#pragma unroll
            for (int q = 0; q < 8; q++) {
                ulonglong2 wp = w2p[q];
                h2a2[2*q]   = fma2(a0p, wp.x, h2a2[2*q]);
                h2a2[2*q+1] = fma2(a0p, wp.y, h2a2[2*q+1]);
                h2b2[2*q]   = fma2(a1p, wp.x, h2b2[2*q]);
                h2b2[2*q+1] = fma2(a1p, wp.y, h2b2[2*q+1]);
            }
        }
        float o0 = sb3v, o1 = sb3v;
#pragma unroll
        for (int q = 0; q < 16; q++) {
            float xa, ya, xb, yb;
            unpk2(h2a2[q], xa, ya);
            unpk2(h2b2[q], xb, yb);
            float w3x = sW3[2 * q], w3y = sW3[2 * q + 1];
            o0 = fmaf(xa > 0.f ? xa : 0.f, w3x, o0);
            o0 = fmaf(ya > 0.f ? ya : 0.f, w3y, o0);
            o1 = fmaf(xb > 0.f ? xb : 0.f, w3x, o1);
            o1 = fmaf(yb > 0.f ? yb : 0.f, w3y, o1);
        }
        float u0 = fmaxf(o0, 0.f) + log1pf(expf(-fabsf(o0)));
        float u1 = fmaxf(o1, 0.f) + log1pf(expf(-fabsf(o1)));
        out[OFF_U + base + i0] = u0;
        out[OFF_U + base + i1] = u1;
        uv[bi * 2] = u0; uv[bi * 2 + 1] = u1;
    }

    sRed[tid] = eSum;
    __syncthreads();
    for (int w = 128; w > 0; w >>= 1) {
        if (tid < w) sRed[tid] += sRed[tid + w];
        __syncthreads();
    }
    if (tid == 0) sTe = sRed[0];
    __syncthreads();
    const float te = sTe + 1e-8f;

#pragma unroll
    for (int b = 0; b < 4; b++) {
        int idx = tid + b * 256;
        float F = ev[b] / te;
        out[OFF_F + base + idx] = F;
        out[OFF_W + base + idx] = F * uv[b];
    }
}

// ===========================================================================
// K3: per-mode stats (unchanged, known-good).
// ===========================================================================
__global__ __launch_bounds__(256) void k_stats(float* __restrict__ out)
{
    __shared__ double red[6][256];
    const int tid = threadIdx.x;
    const int kl  = tid & 7;
    const int sg  = tid >> 3;                 // 0..31
    const int k   = blockIdx.x * 8 + kl;

    double su = 0, se = 0, sen = 0, sue = 0, suu = 0, see = 0;
    for (int s = sg; s < NIMG; s += 32) {
        float u  = out[OFF_U   + (size_t)s * 1024 + k];
        float e  = out[OFF_ERR + (size_t)s * 1024 + k];
        float en = out[OFF_E   + (size_t)s * 1024 + k];
        su += u; se += e; sen += en;
        sue += (double)u * (double)e;
        suu += (double)u * (double)u;
        see += (double)e * (double)e;
    }
    red[0][tid] = su;  red[1][tid] = se;  red[2][tid] = sen;
    red[3][tid] = sue; red[4][tid] = suu; red[5][tid] = see;
    __syncthreads();

    for (int off = 16; off >= 1; off >>= 1) {
        if (sg < off) {
#pragma unroll
            for (int m = 0; m < 6; m++)
                red[m][tid] += red[m][tid + off * 8];
        }
        __syncthreads();
    }
    if (tid < 8) {
        double tsu = red[0][tid], tse = red[1][tid], tsen = red[2][tid];
        double tsue = red[3][tid], tsuu = red[4][tid], tsee = red[5][tid];
        out[OFF_US + k] = (float)(tsu  * (1.0 / 512.0));
        out[OFF_ES + k] = (float)(tsen * (1.0 / 512.0));
        double num  = tsue - tsu * tse * (1.0 / 512.0);
        double varu = tsuu - tsu * tsu * (1.0 / 512.0);
        double vare = tsee - tse * tse * (1.0 / 512.0);
        out[OFF_CAL + k] = (float)(num / (sqrt(varu * vare) + 1e-8));
    }
}

// ---------------------------------------------------------------------------
extern "C" void kernel_launch(void* const* d_in, const int* in_sizes, int n_in,
                              void* d_out, int out_size)
{
    const float* pred = (const float*)d_in[0];
    // d_in[1] = uncertainty: unused by the reference
    const float* gt   = (const float*)d_in[2];
    const float* W1   = (const float*)d_in[3];
    const float* b1   = (const float*)d_in[4];
    const float* W2   = (const float*)d_in[5];
    const float* b2   = (const float*)d_in[6];
    const float* W3   = (const float*)d_in[7];
    const float* b3   = (const float*)d_in[8];
    float* out = (float*)d_out;

    const int smemA = A_FLOATS * 4;   // 50176 B
    const int smemB = B_FLOATS * 4;   // 82928 B
    cudaFuncSetAttribute(k_stA, cudaFuncAttributeMaxDynamicSharedMemorySize, smemA);
    cudaFuncSetAttribute(k_stB, cudaFuncAttributeMaxDynamicSharedMemorySize, smemB);

    k_stA<<<1024, 256, smemA>>>(pred, gt);
    k_stB<<<1024, 512, smemB>>>();
    k_mlp_epi<<<512, 256>>>(W1, b1, W2, b2, W3, b3, out);
    k_stats<<<128, 256>>>(out);
}